// round 2
// baseline (speedup 1.0000x reference)
#include <cuda_runtime.h>
#include <cuda_bf16.h>
#include <math.h>

#define DEPTH 12
#define HEADS 12
#define DIM 768
#define NTOK 1025
#define NUM_REL 3972
#define BTOK (2 * NTOK)            // 2050 rows
#define FEAT (2 * NTOK * DIM)      // per-feat floats

// ---------------- scratch (static device globals; no allocation) ----------------
__device__ float g_t[FEAT];
__device__ float g_h[FEAT];
__device__ float g_qkv[2 * NTOK * 3 * DIM];
__device__ float g_o[FEAT];
__device__ float g_mlp[2 * NTOK * 4 * DIM];
__device__ float g_feats[4 * FEAT];
__device__ float g_qkvbias[3 * DIM];
__device__ float g_wt[4 * DIM * DIM];          // transposed deconv weight [3072,768]
__device__ float g_gemm[8192 * 3072];          // biggest deconv GEMM out
__device__ float g_y1cl[2 * 64 * 64 * DIM];    // fpn1 mid, channel-last

__device__ __forceinline__ float gelu_exact(float x) {
    return 0.5f * x * (1.0f + erff(x * 0.70710678118654752f));
}

// ---------------- patch embed ----------------
__global__ void patch_embed_kernel(const float* __restrict__ x,
                                   const float* __restrict__ pw,
                                   const float* __restrict__ pb,
                                   const float* __restrict__ pos,
                                   float* __restrict__ t) {
    __shared__ float sp[768];
    int gx = blockIdx.x, gy = blockIdx.y, b = blockIdx.z;
    int tid = threadIdx.x;
    const float* xb = x + (long)b * 3 * 512 * 512;
    for (int e = tid; e < 768; e += 256) {
        int c = e >> 8, rem = e & 255, i = rem >> 4, j = rem & 15;
        sp[e] = xb[c * 262144 + (gy * 16 + i) * 512 + gx * 16 + j];
    }
    __syncthreads();
    int tok = gy * 32 + gx;
    for (int d = tid; d < 768; d += 256) {
        const float* wr = pw + (long)d * 768;
        float acc = 0.f;
#pragma unroll 8
        for (int k = 0; k < 768; k++) acc += wr[k] * sp[k];
        t[((long)(b * NTOK) + 1 + tok) * DIM + d] = acc + pb[d] + pos[(1 + tok) * DIM + d];
    }
}

__global__ void cls_kernel(const float* __restrict__ cls, const float* __restrict__ pos,
                           float* __restrict__ t) {
    int d = blockIdx.x * blockDim.x + threadIdx.x;
    if (d < DIM) {
        t[d] = cls[d] + pos[d];
        t[(long)NTOK * DIM + d] = cls[d] + pos[d];
    }
}

// ---------------- layernorm (row per block, 768 cols) ----------------
__global__ void ln_kernel(const float* __restrict__ x, const float* __restrict__ w,
                          const float* __restrict__ b, float* __restrict__ y) {
    long row = blockIdx.x;
    const float* xr = x + row * DIM;
    int tid = threadIdx.x;
    float v0 = xr[tid], v1 = xr[tid + 256], v2 = xr[tid + 512];
    float s = v0 + v1 + v2;
    float sq = v0 * v0 + v1 * v1 + v2 * v2;
    __shared__ float rs[256], rq[256];
    rs[tid] = s; rq[tid] = sq;
    __syncthreads();
    for (int off = 128; off > 0; off >>= 1) {
        if (tid < off) { rs[tid] += rs[tid + off]; rq[tid] += rq[tid + off]; }
        __syncthreads();
    }
    __shared__ float mean_s, inv_s;
    if (tid == 0) {
        float m = rs[0] * (1.0f / 768.0f);
        float var = rq[0] * (1.0f / 768.0f) - m * m;
        mean_s = m;
        inv_s = rsqrtf(var + 1e-6f);
    }
    __syncthreads();
    float m = mean_s, inv = inv_s;
    float* yr = y + row * DIM;
    yr[tid]       = (v0 - m) * inv * w[tid]       + b[tid];
    yr[tid + 256] = (v1 - m) * inv * w[tid + 256] + b[tid + 256];
    yr[tid + 512] = (v2 - m) * inv * w[tid + 512] + b[tid + 512];
}

// ---------------- qkv bias assembly ----------------
__global__ void qkvbias_kernel(const float* __restrict__ qb, const float* __restrict__ vb,
                               float* __restrict__ ob) {
    int i = blockIdx.x * blockDim.x + threadIdx.x;
    if (i >= 3 * DIM) return;
    if (i < DIM) ob[i] = qb[i];
    else if (i < 2 * DIM) ob[i] = 0.f;
    else ob[i] = vb[i - 2 * DIM];
}

// ---------------- generic SGEMM: C = A @ W^T + bias (+res) (+gelu) ----------------
// A: [M,K], W: [N,K], C/res: [M,N]. N % 128 == 0, K % 8 == 0 required.
__global__ void __launch_bounds__(256, 2) gemm_kernel(
    const float* __restrict__ A, const float* __restrict__ W,
    const float* __restrict__ bias, const float* __restrict__ res,
    float* __restrict__ C, int M, int N, int K, int act) {
    __shared__ float As[8][128];
    __shared__ float Bs[8][128];
    int bm = blockIdx.y, bn = blockIdx.x;
    int t = threadIdx.x;
    int tx = t & 15, ty = t >> 4;
    int row0 = bm * 128, col0 = bn * 128;
    int arow = t >> 1;
    int acol = (t & 1) * 4;
    const float* Ab = A + (long)(row0 + arow) * K + acol;
    const float* Wb = W + (long)(col0 + arow) * K + acol;
    bool aval = (row0 + arow) < M;
    bool wval = (col0 + arow) < N;
    float acc[8][8];
#pragma unroll
    for (int i = 0; i < 8; i++)
#pragma unroll
        for (int j = 0; j < 8; j++) acc[i][j] = 0.f;

    for (int k0 = 0; k0 < K; k0 += 8) {
        float4 av = aval ? *(const float4*)(Ab + k0) : make_float4(0, 0, 0, 0);
        float4 wv = wval ? *(const float4*)(Wb + k0) : make_float4(0, 0, 0, 0);
        As[acol + 0][arow] = av.x; As[acol + 1][arow] = av.y;
        As[acol + 2][arow] = av.z; As[acol + 3][arow] = av.w;
        Bs[acol + 0][arow] = wv.x; Bs[acol + 1][arow] = wv.y;
        Bs[acol + 2][arow] = wv.z; Bs[acol + 3][arow] = wv.w;
        __syncthreads();
#pragma unroll
        for (int kk = 0; kk < 8; kk++) {
            float4 a0 = *(float4*)&As[kk][ty * 4];
            float4 a1 = *(float4*)&As[kk][ty * 4 + 64];
            float4 b0 = *(float4*)&Bs[kk][tx * 4];
            float4 b1 = *(float4*)&Bs[kk][tx * 4 + 64];
            float ar[8] = {a0.x, a0.y, a0.z, a0.w, a1.x, a1.y, a1.z, a1.w};
            float br[8] = {b0.x, b0.y, b0.z, b0.w, b1.x, b1.y, b1.z, b1.w};
#pragma unroll
            for (int i = 0; i < 8; i++)
#pragma unroll
                for (int j = 0; j < 8; j++) acc[i][j] += ar[i] * br[j];
        }
        __syncthreads();
    }
#pragma unroll
    for (int i = 0; i < 8; i++) {
        int m = row0 + ((i < 4) ? (ty * 4 + i) : (64 + ty * 4 + (i - 4)));
        if (m >= M) continue;
#pragma unroll
        for (int j = 0; j < 8; j++) {
            int n = col0 + ((j < 4) ? (tx * 4 + j) : (64 + tx * 4 + (j - 4)));
            if (n >= N) continue;
            float v = acc[i][j];
            if (bias) v += bias[n];
            if (res) v += res[(long)m * N + n];
            if (act == 1) v = gelu_exact(v);
            C[(long)m * N + n] = v;
        }
    }
}

// ---------------- fused attention: scores + rel bias + softmax + AV ----------------
// grid: (ceil(NTOK/8), HEADS, B). 256 threads.
__global__ void __launch_bounds__(256) attn_kernel(
    const float* __restrict__ qkv, const float* __restrict__ relT,
    const int* __restrict__ relIdx, float* __restrict__ out) {
    __shared__ float sQ[8][64];
    __shared__ float sK[32][65];
    __shared__ float sS[8][NTOK];
    int it = blockIdx.x, hh = blockIdx.y, b = blockIdx.z;
    int t = threadIdx.x;
    int i0 = it * 8;

    for (int e = t; e < 8 * 64; e += 256) {
        int r = e >> 6, d = e & 63;
        int i = i0 + r;
        sQ[r][d] = (i < NTOK) ? qkv[((long)(b * NTOK + i)) * (3 * DIM) + hh * 64 + d] * 0.125f : 0.f;
    }
    __syncthreads();

    int rr = t >> 5;
    int jj = t & 31;
    for (int jt = 0; jt < NTOK; jt += 32) {
        for (int e = t; e < 32 * 64; e += 256) {
            int kr = e >> 6, d = e & 63;
            int j = jt + kr;
            sK[kr][d] = (j < NTOK) ? qkv[((long)(b * NTOK + j)) * (3 * DIM) + DIM + hh * 64 + d] : 0.f;
        }
        __syncthreads();
        int i = i0 + rr, j = jt + jj;
        if (i < NTOK && j < NTOK) {
            float s = 0.f;
#pragma unroll
            for (int d = 0; d < 64; d++) s += sQ[rr][d] * sK[jj][d];
            int ridx = relIdx[(long)i * NTOK + j];
            s += relT[ridx * HEADS + hh];
            sS[rr][j] = s;
        }
        __syncthreads();
    }

    // softmax: warp w owns row w
    int w = t >> 5, lane = t & 31;
    if (i0 + w < NTOK) {
        float mx = -1e30f;
        for (int j = lane; j < NTOK; j += 32) mx = fmaxf(mx, sS[w][j]);
#pragma unroll
        for (int off = 16; off > 0; off >>= 1) mx = fmaxf(mx, __shfl_xor_sync(0xffffffff, mx, off));
        float sum = 0.f;
        for (int j = lane; j < NTOK; j += 32) {
            float e = __expf(sS[w][j] - mx);
            sS[w][j] = e;
            sum += e;
        }
#pragma unroll
        for (int off = 16; off > 0; off >>= 1) sum += __shfl_xor_sync(0xffffffff, sum, off);
        float inv = 1.0f / sum;
        for (int j = lane; j < NTOK; j += 32) sS[w][j] *= inv;
    }
    __syncthreads();

    // AV: thread -> (r2, dd) and (r2+4, dd)
    int r2 = t >> 6;
    int dd = t & 63;
    float acc0 = 0.f, acc1 = 0.f;
    for (int jt = 0; jt < NTOK; jt += 32) {
        for (int e = t; e < 32 * 64; e += 256) {
            int kr = e >> 6, d = e & 63;
            int j = jt + kr;
            sK[kr][d] = (j < NTOK) ? qkv[((long)(b * NTOK + j)) * (3 * DIM) + 2 * DIM + hh * 64 + d] : 0.f;
        }
        __syncthreads();
        int lim = NTOK - jt; if (lim > 32) lim = 32;
        for (int kr = 0; kr < lim; kr++) {
            acc0 += sS[r2][jt + kr] * sK[kr][dd];
            acc1 += sS[r2 + 4][jt + kr] * sK[kr][dd];
        }
        __syncthreads();
    }
    int ia = i0 + r2;
    if (ia < NTOK) out[((long)(b * NTOK + ia)) * DIM + hh * 64 + dd] = acc0;
    if (ia + 4 < NTOK) out[((long)(b * NTOK + ia + 4)) * DIM + hh * 64 + dd] = acc1;
}

// ---------------- deconv weight transpose: wt[(ij*768+dout), c] = w[c, dout, i, j] ----
__global__ void transw_kernel(const float* __restrict__ w, float* __restrict__ wt) {
    int idx = blockIdx.x * blockDim.x + threadIdx.x;
    if (idx >= 3072 * 768) return;
    int n = idx / 768, c = idx % 768;
    int dout = n % 768, ij = n / 768;
    wt[idx] = w[(long)c * 3072 + dout * 4 + ij];
}

// ---------------- fpn1 mid scatter: +bias, BN(eval), GELU -> channel-last 64x64 -----
__global__ void scatter_mid_kernel(const float* __restrict__ G, const float* __restrict__ bias,
                                   const float* __restrict__ bnw, const float* __restrict__ bnb,
                                   const float* __restrict__ bnm, const float* __restrict__ bnv,
                                   float* __restrict__ y1) {
    int idx = blockIdx.x * blockDim.x + threadIdx.x;
    const int total = 2 * 1024 * 3072;
    if (idx >= total) return;
    int p = idx / 3072, n = idx % 3072;
    int b = p >> 10, hw = p & 1023, h = hw >> 5, wq = hw & 31;
    int ij = n / 768, dout = n % 768, i = ij >> 1, j = ij & 1;
    float val = G[idx] + bias[dout];
    val = (val - bnm[dout]) * rsqrtf(bnv[dout] + 1e-5f) * bnw[dout] + bnb[dout];
    val = gelu_exact(val);
    y1[(((long)b * 64 + (2 * h + i)) * 64 + (2 * wq + j)) * 768 + dout] = val;
}

__global__ void scatter_o1_kernel(const float* __restrict__ G, const float* __restrict__ bias,
                                  float* __restrict__ out) {
    int idx = blockIdx.x * blockDim.x + threadIdx.x;
    const int total = 8192 * 3072;
    if (idx >= total) return;
    int p = idx / 3072, n = idx % 3072;
    int b = p >> 12, yx = p & 4095, yy = yx >> 6, xx = yx & 63;
    int ij = n / 768, dout = n % 768, i = ij >> 1, j = ij & 1;
    float val = G[idx] + bias[dout];
    out[((long)(b * 768 + dout) << 14) + (2 * yy + i) * 128 + (2 * xx + j)] = val;
}

__global__ void scatter_o2_kernel(const float* __restrict__ G, const float* __restrict__ bias,
                                  float* __restrict__ out) {
    int idx = blockIdx.x * blockDim.x + threadIdx.x;
    const int total = 2 * 1024 * 3072;
    if (idx >= total) return;
    int p = idx / 3072, n = idx % 3072;
    int b = p >> 10, hw = p & 1023, h = hw >> 5, wq = hw & 31;
    int ij = n / 768, dout = n % 768, i = ij >> 1, j = ij & 1;
    float val = G[idx] + bias[dout];
    out[((long)(b * 768 + dout) << 12) + (2 * h + i) * 64 + (2 * wq + j)] = val;
}

__global__ void o3_kernel(const float* __restrict__ feat, float* __restrict__ out) {
    int idx = blockIdx.x * blockDim.x + threadIdx.x;
    const int total = 2 * 768 * 1024;
    if (idx >= total) return;
    int b = idx / (768 * 1024), rem = idx % (768 * 1024);
    int d = rem / 1024, yx = rem % 1024;
    out[idx] = feat[((long)b * NTOK + 1 + yx) * DIM + d];
}

__global__ void o4_kernel(const float* __restrict__ feat, float* __restrict__ out) {
    int idx = blockIdx.x * blockDim.x + threadIdx.x;
    const int total = 2 * 768 * 256;
    if (idx >= total) return;
    int b = idx / (768 * 256), rem = idx % (768 * 256);
    int d = rem / 256, hw = rem % 256;
    int h = hw >> 4, wq = hw & 15;
    float m = -1e30f;
#pragma unroll
    for (int i = 0; i < 2; i++)
#pragma unroll
        for (int j = 0; j < 2; j++) {
            int tok = 1 + (2 * h + i) * 32 + (2 * wq + j);
            float v = feat[((long)b * NTOK + tok) * DIM + d];
            m = fmaxf(m, v);
        }
    out[idx] = m;
}

// ---------------- host orchestration ----------------
extern "C" void kernel_launch(void* const* d_in, const int* in_sizes, int n_in,
                              void* d_out, int out_size) {
    const float* x        = (const float*)d_in[0];
    const float* patch_w  = (const float*)d_in[1];
    const float* patch_b  = (const float*)d_in[2];
    const float* cls_tok  = (const float*)d_in[3];
    const float* pos      = (const float*)d_in[4];
    const float* ln1_w    = (const float*)d_in[5];
    const float* ln1_b    = (const float*)d_in[6];
    const float* qkv_w    = (const float*)d_in[7];
    const float* q_bias   = (const float*)d_in[8];
    const float* v_bias   = (const float*)d_in[9];
    const float* rel_tab  = (const float*)d_in[10];
    const float* proj_w   = (const float*)d_in[11];
    const float* proj_b   = (const float*)d_in[12];
    const float* ln2_w    = (const float*)d_in[13];
    const float* ln2_b    = (const float*)d_in[14];
    const float* fc1_w    = (const float*)d_in[15];
    const float* fc1_b    = (const float*)d_in[16];
    const float* fc2_w    = (const float*)d_in[17];
    const float* fc2_b    = (const float*)d_in[18];
    const float* d1_w     = (const float*)d_in[19];
    const float* d1_b     = (const float*)d_in[20];
    const float* bn_w     = (const float*)d_in[21];
    const float* bn_b     = (const float*)d_in[22];
    const float* bn_mean  = (const float*)d_in[23];
    const float* bn_var   = (const float*)d_in[24];
    const float* d2_w     = (const float*)d_in[25];
    const float* d2_b     = (const float*)d_in[26];
    const float* f2_w     = (const float*)d_in[27];
    const float* f2_b     = (const float*)d_in[28];
    const int*   rel_idx  = (const int*)d_in[29];
    float* out = (float*)d_out;

    float *t_, *h_, *qkv_, *o_, *mlp_, *feats_, *qb_, *wt_, *gm_, *y1_;
    cudaGetSymbolAddress((void**)&t_,   g_t);
    cudaGetSymbolAddress((void**)&h_,   g_h);
    cudaGetSymbolAddress((void**)&qkv_, g_qkv);
    cudaGetSymbolAddress((void**)&o_,   g_o);
    cudaGetSymbolAddress((void**)&mlp_, g_mlp);
    cudaGetSymbolAddress((void**)&feats_, g_feats);
    cudaGetSymbolAddress((void**)&qb_,  g_qkvbias);
    cudaGetSymbolAddress((void**)&wt_,  g_wt);
    cudaGetSymbolAddress((void**)&gm_,  g_gemm);
    cudaGetSymbolAddress((void**)&y1_,  g_y1cl);

    // patch embed + cls + pos
    patch_embed_kernel<<<dim3(32, 32, 2), 256>>>(x, patch_w, patch_b, pos, t_);
    cls_kernel<<<3, 256>>>(cls_tok, pos, t_);

    const int OUT_IDX[4] = {3, 5, 7, 11};
    int feat_k = 0;
    for (int l = 0; l < DEPTH; l++) {
        ln_kernel<<<BTOK, 256>>>(t_, ln1_w + l * DIM, ln1_b + l * DIM, h_);
        qkvbias_kernel<<<9, 256>>>(q_bias + l * DIM, v_bias + l * DIM, qb_);
        gemm_kernel<<<dim3(18, 17), 256>>>(h_, qkv_w + (long)l * 3 * DIM * DIM, qb_,
                                           nullptr, qkv_, BTOK, 3 * DIM, DIM, 0);
        attn_kernel<<<dim3(129, HEADS, 2), 256>>>(qkv_, rel_tab + (long)l * NUM_REL * HEADS,
                                                  rel_idx, o_);
        gemm_kernel<<<dim3(6, 17), 256>>>(o_, proj_w + (long)l * DIM * DIM, proj_b + l * DIM,
                                          t_, t_, BTOK, DIM, DIM, 0);
        ln_kernel<<<BTOK, 256>>>(t_, ln2_w + l * DIM, ln2_b + l * DIM, h_);
        gemm_kernel<<<dim3(24, 17), 256>>>(h_, fc1_w + (long)l * 4 * DIM * DIM, fc1_b + l * 4 * DIM,
                                           nullptr, mlp_, BTOK, 4 * DIM, DIM, 1);
        gemm_kernel<<<dim3(6, 17), 256>>>(mlp_, fc2_w + (long)l * DIM * 4 * DIM, fc2_b + l * DIM,
                                          t_, t_, BTOK, DIM, 4 * DIM, 0);
        if (feat_k < 4 && l == OUT_IDX[feat_k]) {
            cudaMemcpyAsync(feats_ + (long)feat_k * FEAT, t_, (long)FEAT * sizeof(float),
                            cudaMemcpyDeviceToDevice);
            feat_k++;
        }
    }

    const long O1 = 2L * 768 * 128 * 128;
    const long O2 = 2L * 768 * 64 * 64;
    const long O3 = 2L * 768 * 32 * 32;

    // fpn1 stage A: deconv d1 on feats[0]
    transw_kernel<<<(3072 * 768 + 255) / 256, 256>>>(d1_w, wt_);
    for (int b = 0; b < 2; b++)
        gemm_kernel<<<dim3(24, 8), 256>>>(feats_ + 0L * FEAT + (long)b * NTOK * DIM + DIM, wt_,
                                          nullptr, nullptr, gm_ + (long)b * 1024 * 3072,
                                          1024, 3072, DIM, 0);
    scatter_mid_kernel<<<(2 * 1024 * 3072 + 255) / 256, 256>>>(gm_, d1_b, bn_w, bn_b,
                                                               bn_mean, bn_var, y1_);
    // fpn1 stage B: deconv d2 -> o1
    transw_kernel<<<(3072 * 768 + 255) / 256, 256>>>(d2_w, wt_);
    gemm_kernel<<<dim3(24, 64), 256>>>(y1_, wt_, nullptr, nullptr, gm_, 8192, 3072, DIM, 0);
    scatter_o1_kernel<<<(8192 * 3072 + 255) / 256, 256>>>(gm_, d2_b, out);

    // fpn2: deconv f2 on feats[1] -> o2
    transw_kernel<<<(3072 * 768 + 255) / 256, 256>>>(f2_w, wt_);
    for (int b = 0; b < 2; b++)
        gemm_kernel<<<dim3(24, 8), 256>>>(feats_ + 1L * FEAT + (long)b * NTOK * DIM + DIM, wt_,
                                          nullptr, nullptr, gm_ + (long)b * 1024 * 3072,
                                          1024, 3072, DIM, 0);
    scatter_o2_kernel<<<(2 * 1024 * 3072 + 255) / 256, 256>>>(gm_, f2_b, out + O1);

    // o3: identity map of feats[2]
    o3_kernel<<<(2 * 768 * 1024 + 255) / 256, 256>>>(feats_ + 2L * FEAT, out + O1 + O2);
    // o4: 2x2 maxpool of feats[3]
    o4_kernel<<<(2 * 768 * 256 + 255) / 256, 256>>>(feats_ + 3L * FEAT, out + O1 + O2 + O3);
}

// round 5
// speedup vs baseline: 1.2048x; 1.2048x over previous
#include <cuda_runtime.h>
#include <cuda_bf16.h>
#include <math.h>
#include <stdint.h>

#define DEPTH 12
#define HEADS 12
#define DIM 768
#define NTOK 1025
#define NUM_REL 3972
#define BTOK (2 * NTOK)            // 2050 rows
#define FEAT (2 * NTOK * DIM)      // per-feat floats

// ---------------- scratch (static device globals; no allocation) ----------------
__device__ float g_t[FEAT];
__device__ float g_qkv[2 * NTOK * 3 * DIM];
__device__ float g_feats[4 * FEAT];
__device__ float g_qkvbias[3 * DIM];
__device__ float g_wt[4 * DIM * DIM];              // transposed deconv weight fp32
__device__ float g_gemm[8192 * 3072];              // deconv GEMM fp32 out
// bf16 hi/lo operand buffers
__device__ __nv_bfloat16 g_xh[BTOK * DIM];
__device__ __nv_bfloat16 g_xl[BTOK * DIM];
__device__ __nv_bfloat16 g_yh[2050 * 3072];
__device__ __nv_bfloat16 g_yl[2050 * 3072];
__device__ __nv_bfloat16 g_wh[3072 * 768];
__device__ __nv_bfloat16 g_wl[3072 * 768];

__device__ __forceinline__ float gelu_exact(float x) {
    return 0.5f * x * (1.0f + erff(x * 0.70710678118654752f));
}

__device__ __forceinline__ uint32_t smem_u32(const void* p) {
    uint32_t a;
    asm("{ .reg .u64 tmp; cvta.to.shared.u64 tmp, %1; cvt.u32.u64 %0, tmp; }"
        : "=r"(a) : "l"(p));
    return a;
}

__device__ __forceinline__ void ldmx4(uint32_t* r, uint32_t addr) {
    asm volatile("ldmatrix.sync.aligned.m8n8.x4.shared.b16 {%0,%1,%2,%3}, [%4];"
                 : "=r"(r[0]), "=r"(r[1]), "=r"(r[2]), "=r"(r[3]) : "r"(addr));
}

__device__ __forceinline__ void mma16816(float* d, const uint32_t* a, const uint32_t* b) {
    asm volatile(
        "mma.sync.aligned.m16n8k16.row.col.f32.bf16.bf16.f32 "
        "{%0,%1,%2,%3}, {%4,%5,%6,%7}, {%8,%9}, {%0,%1,%2,%3};"
        : "+f"(d[0]), "+f"(d[1]), "+f"(d[2]), "+f"(d[3])
        : "r"(a[0]), "r"(a[1]), "r"(a[2]), "r"(a[3]), "r"(b[0]), "r"(b[1]));
}

// ---------------- HMMA GEMM: C = (Ah+Al)(Bh+Bl)^T via 3 bf16 passes ----------------
// A: [M,K] bf16 hi/lo, B: [N,K] bf16 hi/lo. N % 128 == 0, K % 32 == 0.
#define LDT 40   // smem row stride in bf16 (32 data + 8 pad) -> conflict-free ldmatrix

__global__ void __launch_bounds__(256) gemm_mma_kernel(
    const __nv_bfloat16* __restrict__ Ah, const __nv_bfloat16* __restrict__ Al,
    const __nv_bfloat16* __restrict__ Bh, const __nv_bfloat16* __restrict__ Bl,
    const float* __restrict__ bias, const float* __restrict__ res,
    float* __restrict__ C, __nv_bfloat16* __restrict__ Ch, __nv_bfloat16* __restrict__ Cl,
    int M, int N, int K, int act) {
    __shared__ __nv_bfloat16 sA[2][128 * LDT];
    __shared__ __nv_bfloat16 sB[2][128 * LDT];
    int t = threadIdx.x, wid = t >> 5, lane = t & 31;
    int row0 = blockIdx.y * 128, col0 = blockIdx.x * 128;
    int m0 = (wid >> 1) * 32, n0 = (wid & 1) * 64;

    float acc[2][8][4];
#pragma unroll
    for (int i = 0; i < 2; i++)
#pragma unroll
        for (int j = 0; j < 8; j++)
#pragma unroll
            for (int c = 0; c < 4; c++) acc[i][j][c] = 0.f;

    const int KC = K >> 5;
    const int NC = 3 * KC;

    auto load_chunk = [&](int buf, int i) {
        int p = i / KC, kc = i - p * KC;
        const __nv_bfloat16* As = (p < 2) ? Ah : Al;
        const __nv_bfloat16* Bs = (p == 1) ? Bl : Bh;
        long kb = (long)kc * 32;
#pragma unroll
        for (int u = 0; u < 2; u++) {
            int unit = t + u * 256;            // 0..511
            int r = unit >> 2, seg = unit & 3;
            int gr = row0 + r;
            uint4 v = make_uint4(0, 0, 0, 0);
            if (gr < M) v = *(const uint4*)(As + (long)gr * K + kb + seg * 8);
            *(uint4*)&sA[buf][r * LDT + seg * 8] = v;
        }
#pragma unroll
        for (int u = 0; u < 2; u++) {
            int unit = t + u * 256;
            int r = unit >> 2, seg = unit & 3;
            uint4 v = *(const uint4*)(Bs + (long)(col0 + r) * K + kb + seg * 8);
            *(uint4*)&sB[buf][r * LDT + seg * 8] = v;
        }
    };

    load_chunk(0, 0);
    __syncthreads();
    for (int i = 0; i < NC; i++) {
        int cur = i & 1;
        if (i + 1 < NC) load_chunk(cur ^ 1, i + 1);
#pragma unroll
        for (int ks = 0; ks < 2; ks++) {
            int kst = ks * 16;
            uint32_t a[2][4];
#pragma unroll
            for (int am = 0; am < 2; am++) {
                int r = m0 + am * 16 + (lane & 15);
                int kc2 = kst + (lane >> 4) * 8;
                ldmx4(a[am], smem_u32(&sA[cur][r * LDT + kc2]));
            }
            uint32_t b[4][4];
#pragma unroll
            for (int bn = 0; bn < 4; bn++) {
                int r = n0 + bn * 16 + (lane & 7) + ((lane >> 4) << 3);
                int kc2 = kst + ((lane >> 3) & 1) * 8;
                ldmx4(b[bn], smem_u32(&sB[cur][r * LDT + kc2]));
            }
#pragma unroll
            for (int am = 0; am < 2; am++)
#pragma unroll
                for (int nn = 0; nn < 8; nn++)
                    mma16816(acc[am][nn], a[am], &b[nn >> 1][(nn & 1) * 2]);
        }
        __syncthreads();
    }

    // epilogue: c0,c1 at (r, col), c2,c3 at (r+8, col)
#pragma unroll
    for (int am = 0; am < 2; am++) {
        int rb = row0 + m0 + am * 16 + (lane >> 2);
#pragma unroll
        for (int half = 0; half < 2; half++) {
            int r = rb + half * 8;
            if (r >= M) continue;
#pragma unroll
            for (int nn = 0; nn < 8; nn++) {
                int col = col0 + n0 + nn * 8 + (lane & 3) * 2;
                long base = (long)r * N + col;
#pragma unroll
                for (int e = 0; e < 2; e++) {
                    float v = acc[am][nn][half * 2 + e];
                    int n = col + e;
                    if (bias) v += bias[n];
                    if (res)  v += res[base + e];
                    if (act)  v = gelu_exact(v);
                    if (C)    C[base + e] = v;
                    if (Ch) {
                        __nv_bfloat16 hb = __float2bfloat16(v);
                        Ch[base + e] = hb;
                        Cl[base + e] = __float2bfloat16(v - __bfloat162float(hb));
                    }
                }
            }
        }
    }
}

// ---------------- fp32 -> bf16 hi/lo split ----------------
__global__ void split_kernel(const float* __restrict__ x, __nv_bfloat16* __restrict__ hi,
                             __nv_bfloat16* __restrict__ lo, long n) {
    long i = (long)blockIdx.x * 256 + threadIdx.x;
    if (i >= n) return;
    float v = x[i];
    __nv_bfloat16 h = __float2bfloat16(v);
    hi[i] = h;
    lo[i] = __float2bfloat16(v - __bfloat162float(h));
}

// ---------------- patch embed ----------------
__global__ void patch_embed_kernel(const float* __restrict__ x,
                                   const float* __restrict__ pw,
                                   const float* __restrict__ pb,
                                   const float* __restrict__ pos,
                                   float* __restrict__ t) {
    __shared__ float sp[768];
    int gx = blockIdx.x, gy = blockIdx.y, b = blockIdx.z;
    int tid = threadIdx.x;
    const float* xb = x + (long)b * 3 * 512 * 512;
    for (int e = tid; e < 768; e += 256) {
        int c = e >> 8, rem = e & 255, i = rem >> 4, j = rem & 15;
        sp[e] = xb[c * 262144 + (gy * 16 + i) * 512 + gx * 16 + j];
    }
    __syncthreads();
    int tok = gy * 32 + gx;
    for (int d = tid; d < 768; d += 256) {
        const float* wr = pw + (long)d * 768;
        float acc = 0.f;
#pragma unroll 8
        for (int k = 0; k < 768; k++) acc += wr[k] * sp[k];
        t[((long)(b * NTOK) + 1 + tok) * DIM + d] = acc + pb[d] + pos[(1 + tok) * DIM + d];
    }
}

__global__ void cls_kernel(const float* __restrict__ cls, const float* __restrict__ pos,
                           float* __restrict__ t) {
    int d = blockIdx.x * blockDim.x + threadIdx.x;
    if (d < DIM) {
        t[d] = cls[d] + pos[d];
        t[(long)NTOK * DIM + d] = cls[d] + pos[d];
    }
}

// ---------------- layernorm -> bf16 hi/lo ----------------
__global__ void ln_split_kernel(const float* __restrict__ x, const float* __restrict__ w,
                                const float* __restrict__ b,
                                __nv_bfloat16* __restrict__ yh, __nv_bfloat16* __restrict__ yl) {
    long row = blockIdx.x;
    const float* xr = x + row * DIM;
    int tid = threadIdx.x;
    float v0 = xr[tid], v1 = xr[tid + 256], v2 = xr[tid + 512];
    float s = v0 + v1 + v2;
    float sq = v0 * v0 + v1 * v1 + v2 * v2;
    __shared__ float rs[256], rq[256];
    rs[tid] = s; rq[tid] = sq;
    __syncthreads();
    for (int off = 128; off > 0; off >>= 1) {
        if (tid < off) { rs[tid] += rs[tid + off]; rq[tid] += rq[tid + off]; }
        __syncthreads();
    }
    __shared__ float mean_s, inv_s;
    if (tid == 0) {
        float m = rs[0] * (1.0f / 768.0f);
        float var = rq[0] * (1.0f / 768.0f) - m * m;
        mean_s = m;
        inv_s = rsqrtf(var + 1e-6f);
    }
    __syncthreads();
    float m = mean_s, inv = inv_s;
#pragma unroll
    for (int q = 0; q < 3; q++) {
        int c = tid + q * 256;
        float vv = (q == 0) ? v0 : (q == 1) ? v1 : v2;
        float v = (vv - m) * inv * w[c] + b[c];
        __nv_bfloat16 h = __float2bfloat16(v);
        yh[row * DIM + c] = h;
        yl[row * DIM + c] = __float2bfloat16(v - __bfloat162float(h));
    }
}

// ---------------- qkv bias assembly ----------------
__global__ void qkvbias_kernel(const float* __restrict__ qb, const float* __restrict__ vb,
                               float* __restrict__ ob) {
    int i = blockIdx.x * blockDim.x + threadIdx.x;
    if (i >= 3 * DIM) return;
    if (i < DIM) ob[i] = qb[i];
    else if (i < 2 * DIM) ob[i] = 0.f;
    else ob[i] = vb[i - 2 * DIM];
}

// ---------------- fused attention (SIMT fp32) -> bf16 hi/lo out ----------------
__global__ void __launch_bounds__(256) attn_kernel(
    const float* __restrict__ qkv, const float* __restrict__ relT,
    const int* __restrict__ relIdx,
    __nv_bfloat16* __restrict__ oh, __nv_bfloat16* __restrict__ ol) {
    __shared__ float sQ[8][64];
    __shared__ float sK[32][65];
    __shared__ float sS[8][NTOK];
    int it = blockIdx.x, hh = blockIdx.y, b = blockIdx.z;
    int t = threadIdx.x;
    int i0 = it * 8;

    for (int e = t; e < 8 * 64; e += 256) {
        int r = e >> 6, d = e & 63;
        int i = i0 + r;
        sQ[r][d] = (i < NTOK) ? qkv[((long)(b * NTOK + i)) * (3 * DIM) + hh * 64 + d] * 0.125f : 0.f;
    }
    __syncthreads();

    int rr = t >> 5;
    int jj = t & 31;
    for (int jt = 0; jt < NTOK; jt += 32) {
        for (int e = t; e < 32 * 64; e += 256) {
            int kr = e >> 6, d = e & 63;
            int j = jt + kr;
            sK[kr][d] = (j < NTOK) ? qkv[((long)(b * NTOK + j)) * (3 * DIM) + DIM + hh * 64 + d] : 0.f;
        }
        __syncthreads();
        int i = i0 + rr, j = jt + jj;
        if (i < NTOK && j < NTOK) {
            float s = 0.f;
#pragma unroll
            for (int d = 0; d < 64; d++) s += sQ[rr][d] * sK[jj][d];
            int ridx = relIdx[(long)i * NTOK + j];
            s += relT[ridx * HEADS + hh];
            sS[rr][j] = s;
        }
        __syncthreads();
    }

    int w = t >> 5, lane = t & 31;
    if (i0 + w < NTOK) {
        float mx = -1e30f;
        for (int j = lane; j < NTOK; j += 32) mx = fmaxf(mx, sS[w][j]);
#pragma unroll
        for (int off = 16; off > 0; off >>= 1) mx = fmaxf(mx, __shfl_xor_sync(0xffffffff, mx, off));
        float sum = 0.f;
        for (int j = lane; j < NTOK; j += 32) {
            float e = __expf(sS[w][j] - mx);
            sS[w][j] = e;
            sum += e;
        }
#pragma unroll
        for (int off = 16; off > 0; off >>= 1) sum += __shfl_xor_sync(0xffffffff, sum, off);
        float inv = 1.0f / sum;
        for (int j = lane; j < NTOK; j += 32) sS[w][j] *= inv;
    }
    __syncthreads();

    int r2 = t >> 6;
    int dd = t & 63;
    float acc0 = 0.f, acc1 = 0.f;
    for (int jt = 0; jt < NTOK; jt += 32) {
        for (int e = t; e < 32 * 64; e += 256) {
            int kr = e >> 6, d = e & 63;
            int j = jt + kr;
            sK[kr][d] = (j < NTOK) ? qkv[((long)(b * NTOK + j)) * (3 * DIM) + 2 * DIM + hh * 64 + d] : 0.f;
        }
        __syncthreads();
        int lim = NTOK - jt; if (lim > 32) lim = 32;
        for (int kr = 0; kr < lim; kr++) {
            acc0 += sS[r2][jt + kr] * sK[kr][dd];
            acc1 += sS[r2 + 4][jt + kr] * sK[kr][dd];
        }
        __syncthreads();
    }
    int ia = i0 + r2;
    if (ia < NTOK) {
        long o = ((long)(b * NTOK + ia)) * DIM + hh * 64 + dd;
        __nv_bfloat16 h = __float2bfloat16(acc0);
        oh[o] = h; ol[o] = __float2bfloat16(acc0 - __bfloat162float(h));
    }
    if (ia + 4 < NTOK) {
        long o = ((long)(b * NTOK + ia + 4)) * DIM + hh * 64 + dd;
        __nv_bfloat16 h = __float2bfloat16(acc1);
        oh[o] = h; ol[o] = __float2bfloat16(acc1 - __bfloat162float(h));
    }
}

// ---------------- deconv weight transpose ----------------
__global__ void transw_kernel(const float* __restrict__ w, float* __restrict__ wt) {
    int idx = blockIdx.x * blockDim.x + threadIdx.x;
    if (idx >= 3072 * 768) return;
    int n = idx / 768, c = idx % 768;
    int dout = n % 768, ij = n / 768;
    wt[idx] = w[(long)c * 3072 + dout * 4 + ij];
}

// ---------------- fpn1 mid: +bias, BN, GELU -> channel-last bf16 hi/lo ----------------
__global__ void scatter_mid_kernel(const float* __restrict__ G, const float* __restrict__ bias,
                                   const float* __restrict__ bnw, const float* __restrict__ bnb,
                                   const float* __restrict__ bnm, const float* __restrict__ bnv,
                                   __nv_bfloat16* __restrict__ yh, __nv_bfloat16* __restrict__ yl) {
    int idx = blockIdx.x * blockDim.x + threadIdx.x;
    const int total = 2 * 1024 * 3072;
    if (idx >= total) return;
    int p = idx / 3072, n = idx % 3072;
    int b = p >> 10, hw = p & 1023, h = hw >> 5, wq = hw & 31;
    int ij = n / 768, dout = n % 768, i = ij >> 1, j = ij & 1;
    float val = G[idx] + bias[dout];
    val = (val - bnm[dout]) * rsqrtf(bnv[dout] + 1e-5f) * bnw[dout] + bnb[dout];
    val = gelu_exact(val);
    long o = (((long)b * 64 + (2 * h + i)) * 64 + (2 * wq + j)) * 768 + dout;
    __nv_bfloat16 hb = __float2bfloat16(val);
    yh[o] = hb; yl[o] = __float2bfloat16(val - __bfloat162float(hb));
}

__global__ void scatter_o1_kernel(const float* __restrict__ G, const float* __restrict__ bias,
                                  float* __restrict__ out) {
    int idx = blockIdx.x * blockDim.x + threadIdx.x;
    const int total = 8192 * 3072;
    if (idx >= total) return;
    int p = idx / 3072, n = idx % 3072;
    int b = p >> 12, yx = p & 4095, yy = yx >> 6, xx = yx & 63;
    int ij = n / 768, dout = n % 768, i = ij >> 1, j = ij & 1;
    float val = G[idx] + bias[dout];
    out[((long)(b * 768 + dout) << 14) + (2 * yy + i) * 128 + (2 * xx + j)] = val;
}

__global__ void scatter_o2_kernel(const float* __restrict__ G, const float* __restrict__ bias,
                                  float* __restrict__ out) {
    int idx = blockIdx.x * blockDim.x + threadIdx.x;
    const int total = 2 * 1024 * 3072;
    if (idx >= total) return;
    int p = idx / 3072, n = idx % 3072;
    int b = p >> 10, hw = p & 1023, h = hw >> 5, wq = hw & 31;
    int ij = n / 768, dout = n % 768, i = ij >> 1, j = ij & 1;
    float val = G[idx] + bias[dout];
    out[((long)(b * 768 + dout) << 12) + (2 * h + i) * 64 + (2 * wq + j)] = val;
}

__global__ void o3_kernel(const float* __restrict__ feat, float* __restrict__ out) {
    int idx = blockIdx.x * blockDim.x + threadIdx.x;
    const int total = 2 * 768 * 1024;
    if (idx >= total) return;
    int b = idx / (768 * 1024), rem = idx % (768 * 1024);
    int d = rem / 1024, yx = rem % 1024;
    out[idx] = feat[((long)b * NTOK + 1 + yx) * DIM + d];
}

__global__ void o4_kernel(const float* __restrict__ feat, float* __restrict__ out) {
    int idx = blockIdx.x * blockDim.x + threadIdx.x;
    const int total = 2 * 768 * 256;
    if (idx >= total) return;
    int b = idx / (768 * 256), rem = idx % (768 * 256);
    int d = rem / 256, hw = rem % 256;
    int h = hw >> 4, wq = hw & 15;
    float m = -1e30f;
#pragma unroll
    for (int i = 0; i < 2; i++)
#pragma unroll
        for (int j = 0; j < 2; j++) {
            int tok = 1 + (2 * h + i) * 32 + (2 * wq + j);
            float v = feat[((long)b * NTOK + tok) * DIM + d];
            m = fmaxf(m, v);
        }
    out[idx] = m;
}

// ---------------- host orchestration ----------------
extern "C" void kernel_launch(void* const* d_in, const int* in_sizes, int n_in,
                              void* d_out, int out_size) {
    const float* x        = (const float*)d_in[0];
    const float* patch_w  = (const float*)d_in[1];
    const float* patch_b  = (const float*)d_in[2];
    const float* cls_tok  = (const float*)d_in[3];
    const float* pos      = (const float*)d_in[4];
    const float* ln1_w    = (const float*)d_in[5];
    const float* ln1_b    = (const float*)d_in[6];
    const float* qkv_w    = (const float*)d_in[7];
    const float* q_bias   = (const float*)d_in[8];
    const float* v_bias   = (const float*)d_in[9];
    const float* rel_tab  = (const float*)d_in[10];
    const float* proj_w   = (const float*)d_in[11];
    const float* proj_b   = (const float*)d_in[12];
    const float* ln2_w    = (const float*)d_in[13];
    const float* ln2_b    = (const float*)d_in[14];
    const float* fc1_w    = (const float*)d_in[15];
    const float* fc1_b    = (const float*)d_in[16];
    const float* fc2_w    = (const float*)d_in[17];
    const float* fc2_b    = (const float*)d_in[18];
    const float* d1_w     = (const float*)d_in[19];
    const float* d1_b     = (const float*)d_in[20];
    const float* bn_w     = (const float*)d_in[21];
    const float* bn_b     = (const float*)d_in[22];
    const float* bn_mean  = (const float*)d_in[23];
    const float* bn_var   = (const float*)d_in[24];
    const float* d2_w     = (const float*)d_in[25];
    const float* d2_b     = (const float*)d_in[26];
    const float* f2_w     = (const float*)d_in[27];
    const float* f2_b     = (const float*)d_in[28];
    const int*   rel_idx  = (const int*)d_in[29];
    float* out = (float*)d_out;

    float *t_, *qkv_, *feats_, *qb_, *wt_, *gm_;
    __nv_bfloat16 *xh_, *xl_, *yh_, *yl_, *wh_, *wl_;
    cudaGetSymbolAddress((void**)&t_,    g_t);
    cudaGetSymbolAddress((void**)&qkv_,  g_qkv);
    cudaGetSymbolAddress((void**)&feats_, g_feats);
    cudaGetSymbolAddress((void**)&qb_,   g_qkvbias);
    cudaGetSymbolAddress((void**)&wt_,   g_wt);
    cudaGetSymbolAddress((void**)&gm_,   g_gemm);
    cudaGetSymbolAddress((void**)&xh_,   g_xh);
    cudaGetSymbolAddress((void**)&xl_,   g_xl);
    cudaGetSymbolAddress((void**)&yh_,   g_yh);
    cudaGetSymbolAddress((void**)&yl_,   g_yl);
    cudaGetSymbolAddress((void**)&wh_,   g_wh);
    cudaGetSymbolAddress((void**)&wl_,   g_wl);

    patch_embed_kernel<<<dim3(32, 32, 2), 256>>>(x, patch_w, patch_b, pos, t_);
    cls_kernel<<<3, 256>>>(cls_tok, pos, t_);

    const int OUT_IDX[4] = {3, 5, 7, 11};
    int feat_k = 0;
    for (int l = 0; l < DEPTH; l++) {
        ln_split_kernel<<<BTOK, 256>>>(t_, ln1_w + l * DIM, ln1_b + l * DIM, xh_, xl_);
        qkvbias_kernel<<<9, 256>>>(q_bias + l * DIM, v_bias + l * DIM, qb_);
        split_kernel<<<(2304 * 768 + 255) / 256, 256>>>(qkv_w + (long)l * 2304 * 768, wh_, wl_,
                                                        2304L * 768);
        gemm_mma_kernel<<<dim3(18, 17), 256>>>(xh_, xl_, wh_, wl_, qb_, nullptr,
                                               qkv_, nullptr, nullptr, BTOK, 2304, 768, 0);
        attn_kernel<<<dim3(129, HEADS, 2), 256>>>(qkv_, rel_tab + (long)l * NUM_REL * HEADS,
                                                  rel_idx, xh_, xl_);
        split_kernel<<<(768 * 768 + 255) / 256, 256>>>(proj_w + (long)l * 768 * 768, wh_, wl_,
                                                       768L * 768);
        gemm_mma_kernel<<<dim3(6, 17), 256>>>(xh_, xl_, wh_, wl_, proj_b + l * DIM, t_,
                                              t_, nullptr, nullptr, BTOK, 768, 768, 0);
        ln_split_kernel<<<BTOK, 256>>>(t_, ln2_w + l * DIM, ln2_b + l * DIM, xh_, xl_);
        split_kernel<<<(3072 * 768 + 255) / 256, 256>>>(fc1_w + (long)l * 3072 * 768, wh_, wl_,
                                                        3072L * 768);
        gemm_mma_kernel<<<dim3(24, 17), 256>>>(xh_, xl_, wh_, wl_, fc1_b + l * 3072,
                                               nullptr, nullptr, yh_, yl_, BTOK, 3072, 768, 1);
        split_kernel<<<(768 * 3072 + 255) / 256, 256>>>(fc2_w + (long)l * 768 * 3072, wh_, wl_,
                                                        768L * 3072);
        gemm_mma_kernel<<<dim3(6, 17), 256>>>(yh_, yl_, wh_, wl_, fc2_b + l * DIM, t_,
                                              t_, nullptr, nullptr, BTOK, 768, 3072, 0);
        if (feat_k < 4 && l == OUT_IDX[feat_k]) {
            cudaMemcpyAsync(feats_ + (long)feat_k * FEAT, t_, (long)FEAT * sizeof(float),
                            cudaMemcpyDeviceToDevice);
            feat_k++;
        }
    }

    const long O1 = 2L * 768 * 128 * 128;
    const long O2 = 2L * 768 * 64 * 64;
    const long O3 = 2L * 768 * 32 * 32;

    // fpn1 stage A: deconv d1 on feats[0]
    transw_kernel<<<(3072 * 768 + 255) / 256, 256>>>(d1_w, wt_);
    split_kernel<<<(3072 * 768 + 255) / 256, 256>>>(wt_, wh_, wl_, 3072L * 768);
    for (int b = 0; b < 2; b++) {
        split_kernel<<<(1024 * 768 + 255) / 256, 256>>>(
            feats_ + 0L * FEAT + (long)b * NTOK * DIM + DIM, xh_, xl_, 1024L * 768);
        gemm_mma_kernel<<<dim3(24, 8), 256>>>(xh_, xl_, wh_, wl_, nullptr, nullptr,
                                              gm_ + (long)b * 1024 * 3072, nullptr, nullptr,
                                              1024, 3072, 768, 0);
    }
    scatter_mid_kernel<<<(2 * 1024 * 3072 + 255) / 256, 256>>>(gm_, d1_b, bn_w, bn_b,
                                                               bn_mean, bn_var, yh_, yl_);
    // fpn1 stage B: deconv d2 -> o1
    transw_kernel<<<(3072 * 768 + 255) / 256, 256>>>(d2_w, wt_);
    split_kernel<<<(3072 * 768 + 255) / 256, 256>>>(wt_, wh_, wl_, 3072L * 768);
    gemm_mma_kernel<<<dim3(24, 64), 256>>>(yh_, yl_, wh_, wl_, nullptr, nullptr,
                                           gm_, nullptr, nullptr, 8192, 3072, 768, 0);
    scatter_o1_kernel<<<(8192 * 3072 + 255) / 256, 256>>>(gm_, d2_b, out);

    // fpn2: deconv f2 on feats[1] -> o2
    transw_kernel<<<(3072 * 768 + 255) / 256, 256>>>(f2_w, wt_);
    split_kernel<<<(3072 * 768 + 255) / 256, 256>>>(wt_, wh_, wl_, 3072L * 768);
    for (int b = 0; b < 2; b++) {
        split_kernel<<<(1024 * 768 + 255) / 256, 256>>>(
            feats_ + 1L * FEAT + (long)b * NTOK * DIM + DIM, xh_, xl_, 1024L * 768);
        gemm_mma_kernel<<<dim3(24, 8), 256>>>(xh_, xl_, wh_, wl_, nullptr, nullptr,
                                              gm_ + (long)b * 1024 * 3072, nullptr, nullptr,
                                              1024, 3072, 768, 0);
    }
    scatter_o2_kernel<<<(2 * 1024 * 3072 + 255) / 256, 256>>>(gm_, f2_b, out + O1);

    o3_kernel<<<(2 * 768 * 1024 + 255) / 256, 256>>>(feats_ + 2L * FEAT, out + O1 + O2);
    o4_kernel<<<(2 * 768 * 256 + 255) / 256, 256>>>(feats_ + 3L * FEAT, out + O1 + O2 + O3);
}

// round 6
// speedup vs baseline: 1.5033x; 1.2478x over previous
#include <cuda_runtime.h>
#include <cuda_bf16.h>
#include <math.h>
#include <stdint.h>

#define DEPTH 12
#define HEADS 12
#define DIM 768
#define NTOK 1025
#define NUM_REL 3972
#define BTOK (2 * NTOK)            // 2050 rows
#define FEAT (2 * NTOK * DIM)      // per-feat floats

// ---------------- scratch (static device globals; no allocation) ----------------
__device__ float g_t[FEAT];
__device__ float g_feats[4 * FEAT];
__device__ float g_qkvbias[3 * DIM];
__device__ float g_wt[4 * DIM * DIM];              // transposed deconv weight fp32
__device__ float g_gemm[8192 * 3072];              // deconv GEMM fp32 out
// bf16 hi/lo operand buffers
__device__ __nv_bfloat16 g_xh[BTOK * DIM];
__device__ __nv_bfloat16 g_xl[BTOK * DIM];
__device__ __nv_bfloat16 g_yh[2050 * 3072];
__device__ __nv_bfloat16 g_yl[2050 * 3072];
__device__ __nv_bfloat16 g_wh[3072 * 768];
__device__ __nv_bfloat16 g_wl[3072 * 768];

__device__ __forceinline__ float gelu_exact(float x) {
    return 0.5f * x * (1.0f + erff(x * 0.70710678118654752f));
}

__device__ __forceinline__ uint32_t smem_u32(const void* p) {
    uint32_t a;
    asm("{ .reg .u64 tmp; cvta.to.shared.u64 tmp, %1; cvt.u32.u64 %0, tmp; }"
        : "=r"(a) : "l"(p));
    return a;
}

__device__ __forceinline__ void ldmx4(uint32_t* r, uint32_t addr) {
    asm volatile("ldmatrix.sync.aligned.m8n8.x4.shared.b16 {%0,%1,%2,%3}, [%4];"
                 : "=r"(r[0]), "=r"(r[1]), "=r"(r[2]), "=r"(r[3]) : "r"(addr));
}

__device__ __forceinline__ void mma16816(float* d, const uint32_t* a, const uint32_t* b) {
    asm volatile(
        "mma.sync.aligned.m16n8k16.row.col.f32.bf16.bf16.f32 "
        "{%0,%1,%2,%3}, {%4,%5,%6,%7}, {%8,%9}, {%0,%1,%2,%3};"
        : "+f"(d[0]), "+f"(d[1]), "+f"(d[2]), "+f"(d[3])
        : "r"(a[0]), "r"(a[1]), "r"(a[2]), "r"(a[3]), "r"(b[0]), "r"(b[1]));
}

// ---------------- HMMA GEMM: C = (Ah+Al)(Bh+Bl)^T via 3 bf16 passes ----------------
#define LDT 40   // smem row stride in bf16 (32 data + 8 pad)

__global__ void __launch_bounds__(256) gemm_mma_kernel(
    const __nv_bfloat16* __restrict__ Ah, const __nv_bfloat16* __restrict__ Al,
    const __nv_bfloat16* __restrict__ Bh, const __nv_bfloat16* __restrict__ Bl,
    const float* __restrict__ bias, const float* __restrict__ res,
    float* __restrict__ C, __nv_bfloat16* __restrict__ Ch, __nv_bfloat16* __restrict__ Cl,
    int M, int N, int K, int act) {
    __shared__ __nv_bfloat16 sA[2][128 * LDT];
    __shared__ __nv_bfloat16 sB[2][128 * LDT];
    int t = threadIdx.x, wid = t >> 5, lane = t & 31;
    int row0 = blockIdx.y * 128, col0 = blockIdx.x * 128;
    int m0 = (wid >> 1) * 32, n0 = (wid & 1) * 64;

    float acc[2][8][4];
#pragma unroll
    for (int i = 0; i < 2; i++)
#pragma unroll
        for (int j = 0; j < 8; j++)
#pragma unroll
            for (int c = 0; c < 4; c++) acc[i][j][c] = 0.f;

    const int KC = K >> 5;
    const int NC = 3 * KC;

    auto load_chunk = [&](int buf, int i) {
        int p = i / KC, kc = i - p * KC;
        const __nv_bfloat16* As = (p < 2) ? Ah : Al;
        const __nv_bfloat16* Bs = (p == 1) ? Bl : Bh;
        long kb = (long)kc * 32;
#pragma unroll
        for (int u = 0; u < 2; u++) {
            int unit = t + u * 256;
            int r = unit >> 2, seg = unit & 3;
            int gr = row0 + r;
            uint4 v = make_uint4(0, 0, 0, 0);
            if (gr < M) v = *(const uint4*)(As + (long)gr * K + kb + seg * 8);
            *(uint4*)&sA[buf][r * LDT + seg * 8] = v;
        }
#pragma unroll
        for (int u = 0; u < 2; u++) {
            int unit = t + u * 256;
            int r = unit >> 2, seg = unit & 3;
            uint4 v = *(const uint4*)(Bs + (long)(col0 + r) * K + kb + seg * 8);
            *(uint4*)&sB[buf][r * LDT + seg * 8] = v;
        }
    };

    load_chunk(0, 0);
    __syncthreads();
    for (int i = 0; i < NC; i++) {
        int cur = i & 1;
        if (i + 1 < NC) load_chunk(cur ^ 1, i + 1);
#pragma unroll
        for (int ks = 0; ks < 2; ks++) {
            int kst = ks * 16;
            uint32_t a[2][4];
#pragma unroll
            for (int am = 0; am < 2; am++) {
                int r = m0 + am * 16 + (lane & 15);
                int kc2 = kst + (lane >> 4) * 8;
                ldmx4(a[am], smem_u32(&sA[cur][r * LDT + kc2]));
            }
            uint32_t b[4][4];
#pragma unroll
            for (int bn = 0; bn < 4; bn++) {
                int r = n0 + bn * 16 + (lane & 7) + ((lane >> 4) << 3);
                int kc2 = kst + ((lane >> 3) & 1) * 8;
                ldmx4(b[bn], smem_u32(&sB[cur][r * LDT + kc2]));
            }
#pragma unroll
            for (int am = 0; am < 2; am++)
#pragma unroll
                for (int nn = 0; nn < 8; nn++)
                    mma16816(acc[am][nn], a[am], &b[nn >> 1][(nn & 1) * 2]);
        }
        __syncthreads();
    }

#pragma unroll
    for (int am = 0; am < 2; am++) {
        int rb = row0 + m0 + am * 16 + (lane >> 2);
#pragma unroll
        for (int half = 0; half < 2; half++) {
            int r = rb + half * 8;
            if (r >= M) continue;
#pragma unroll
            for (int nn = 0; nn < 8; nn++) {
                int col = col0 + n0 + nn * 8 + (lane & 3) * 2;
                long base = (long)r * N + col;
#pragma unroll
                for (int e = 0; e < 2; e++) {
                    float v = acc[am][nn][half * 2 + e];
                    int n = col + e;
                    if (bias) v += bias[n];
                    if (res)  v += res[base + e];
                    if (act)  v = gelu_exact(v);
                    if (C)    C[base + e] = v;
                    if (Ch) {
                        __nv_bfloat16 hb = __float2bfloat16(v);
                        Ch[base + e] = hb;
                        Cl[base + e] = __float2bfloat16(v - __bfloat162float(hb));
                    }
                }
            }
        }
    }
}

// ---------------- flash HMMA attention ----------------
// grid (9, HEADS, 2); 256 threads = 8 warps x 16 rows. BM=128, BN=64, D=64.
// qkv in bf16 hi/lo [tok][2304]. Output bf16 hi/lo [tok][768].
#define AQS 72
#define ATT_SMEM (55296 * 2)   // bytes

__global__ void __launch_bounds__(256) attn_mma_kernel(
    const __nv_bfloat16* __restrict__ qh, const __nv_bfloat16* __restrict__ ql,
    const float* __restrict__ relT, const int* __restrict__ relIdx,
    __nv_bfloat16* __restrict__ oh, __nv_bfloat16* __restrict__ ol) {
    extern __shared__ __nv_bfloat16 sm[];
    __nv_bfloat16 *sQh = sm,          *sQl = sm + 9216;
    __nv_bfloat16 *sKh = sm + 18432,  *sKl = sm + 23040;
    __nv_bfloat16 *sVh = sm + 27648,  *sVl = sm + 32256;
    __nv_bfloat16 *sPh = sm + 36864,  *sPl = sm + 46080;
    int t = threadIdx.x, w = t >> 5, lane = t & 31;
    int it = blockIdx.x, hh = blockIdx.y, b = blockIdx.z;
    int i0 = it * 128;
    const int LD3 = 3 * DIM;

    // Q tile (scaled by 0.125; exact power-of-2 on hi and lo)
    for (int idx = t; idx < 128 * 64; idx += 256) {
        int r = idx >> 6, d = idx & 63;
        int i = i0 + r;
        float vh = 0.f, vl = 0.f;
        if (i < NTOK) {
            long g = (long)(b * NTOK + i) * LD3 + hh * 64 + d;
            vh = __bfloat162float(qh[g]); vl = __bfloat162float(ql[g]);
        }
        sQh[r * AQS + d] = __float2bfloat16(vh * 0.125f);
        sQl[r * AQS + d] = __float2bfloat16(vl * 0.125f);
    }

    float m0 = -1e30f, m1 = -1e30f, l0 = 0.f, l1 = 0.f;
    float O[8][4];
#pragma unroll
    for (int nf = 0; nf < 8; nf++)
#pragma unroll
        for (int e = 0; e < 4; e++) O[nf][e] = 0.f;

    int ra = i0 + w * 16 + (lane >> 2);
    int rb = ra + 8;

    for (int jt = 0; jt < 17; jt++) {
        int j0 = jt * 64;
        __syncthreads();   // protect K/V/P from previous iteration readers
        // K tile
        for (int idx = t; idx < 64 * 64; idx += 256) {
            int r = idx >> 6, d = idx & 63;
            int j = j0 + r;
            __nv_bfloat16 kh = __float2bfloat16(0.f), kl = kh;
            if (j < NTOK) {
                long g = (long)(b * NTOK + j) * LD3 + DIM + hh * 64 + d;
                kh = qh[g]; kl = ql[g];
            }
            sKh[r * AQS + d] = kh; sKl[r * AQS + d] = kl;
        }
        // V tile transposed: sV[d][j]
        for (int idx = t; idx < 64 * 64; idx += 256) {
            int j = idx >> 6, d = idx & 63;
            int jg = j0 + j;
            __nv_bfloat16 vh = __float2bfloat16(0.f), vl = vh;
            if (jg < NTOK) {
                long g = (long)(b * NTOK + jg) * LD3 + 2 * DIM + hh * 64 + d;
                vh = qh[g]; vl = ql[g];
            }
            sVh[d * AQS + j] = vh; sVl[d * AQS + j] = vl;
        }
        __syncthreads();

        // S = Q K^T, 3 bf16 passes
        float S[8][4];
#pragma unroll
        for (int nf = 0; nf < 8; nf++)
#pragma unroll
            for (int e = 0; e < 4; e++) S[nf][e] = 0.f;
#pragma unroll
        for (int p = 0; p < 3; p++) {
            const __nv_bfloat16* A = (p < 2) ? sQh : sQl;
            const __nv_bfloat16* B = (p == 1) ? sKl : sKh;
#pragma unroll
            for (int kk = 0; kk < 4; kk++) {
                uint32_t a[4];
                ldmx4(a, smem_u32(&A[(w * 16 + (lane & 15)) * AQS + kk * 16 + (lane >> 4) * 8]));
                uint32_t bb[4][4];
#pragma unroll
                for (int bn = 0; bn < 4; bn++)
                    ldmx4(bb[bn], smem_u32(&B[(bn * 16 + (lane & 7) + ((lane >> 4) << 3)) * AQS +
                                              kk * 16 + ((lane >> 3) & 1) * 8]));
#pragma unroll
                for (int nf = 0; nf < 8; nf++)
                    mma16816(S[nf], a, &bb[nf >> 1][(nf & 1) * 2]);
            }
        }

        // rel bias + mask
#pragma unroll
        for (int nf = 0; nf < 8; nf++) {
#pragma unroll
            for (int e = 0; e < 2; e++) {
                int c = j0 + nf * 8 + (lane & 3) * 2 + e;
                if (ra <= 1024 && c <= 1024)
                    S[nf][e] += relT[(long)relIdx[(long)ra * NTOK + c] * HEADS + hh];
                else S[nf][e] = -1e30f;
                if (rb <= 1024 && c <= 1024)
                    S[nf][2 + e] += relT[(long)relIdx[(long)rb * NTOK + c] * HEADS + hh];
                else S[nf][2 + e] = -1e30f;
            }
        }

        // online softmax (rows ra, rb; row group = 4 lanes)
        float mx0 = -1e30f, mx1 = -1e30f;
#pragma unroll
        for (int nf = 0; nf < 8; nf++) {
            mx0 = fmaxf(mx0, fmaxf(S[nf][0], S[nf][1]));
            mx1 = fmaxf(mx1, fmaxf(S[nf][2], S[nf][3]));
        }
        mx0 = fmaxf(mx0, __shfl_xor_sync(0xffffffff, mx0, 1));
        mx0 = fmaxf(mx0, __shfl_xor_sync(0xffffffff, mx0, 2));
        mx1 = fmaxf(mx1, __shfl_xor_sync(0xffffffff, mx1, 1));
        mx1 = fmaxf(mx1, __shfl_xor_sync(0xffffffff, mx1, 2));
        float nm0 = fmaxf(m0, mx0), nm1 = fmaxf(m1, mx1);
        float al0 = __expf(m0 - nm0), al1 = __expf(m1 - nm1);
        float s0 = 0.f, s1 = 0.f;
        int pr0 = w * 16 + (lane >> 2), pr1 = pr0 + 8;
#pragma unroll
        for (int nf = 0; nf < 8; nf++) {
#pragma unroll
            for (int e = 0; e < 2; e++) {
                int cl = nf * 8 + (lane & 3) * 2 + e;
                float p0 = __expf(S[nf][e] - nm0);
                s0 += p0;
                __nv_bfloat16 h0 = __float2bfloat16(p0);
                sPh[pr0 * AQS + cl] = h0;
                sPl[pr0 * AQS + cl] = __float2bfloat16(p0 - __bfloat162float(h0));
                float p1 = __expf(S[nf][2 + e] - nm1);
                s1 += p1;
                __nv_bfloat16 h1 = __float2bfloat16(p1);
                sPh[pr1 * AQS + cl] = h1;
                sPl[pr1 * AQS + cl] = __float2bfloat16(p1 - __bfloat162float(h1));
            }
        }
        s0 += __shfl_xor_sync(0xffffffff, s0, 1);
        s0 += __shfl_xor_sync(0xffffffff, s0, 2);
        s1 += __shfl_xor_sync(0xffffffff, s1, 1);
        s1 += __shfl_xor_sync(0xffffffff, s1, 2);
        l0 = l0 * al0 + s0; l1 = l1 * al1 + s1;
        m0 = nm0; m1 = nm1;
#pragma unroll
        for (int nf = 0; nf < 8; nf++) {
            O[nf][0] *= al0; O[nf][1] *= al0;
            O[nf][2] *= al1; O[nf][3] *= al1;
        }
        __syncthreads();

        // O += P V  (3 bf16 passes)
#pragma unroll
        for (int p = 0; p < 3; p++) {
            const __nv_bfloat16* A = (p < 2) ? sPh : sPl;
            const __nv_bfloat16* B = (p == 1) ? sVl : sVh;
#pragma unroll
            for (int kk = 0; kk < 4; kk++) {
                uint32_t a[4];
                ldmx4(a, smem_u32(&A[(w * 16 + (lane & 15)) * AQS + kk * 16 + (lane >> 4) * 8]));
                uint32_t bb[4][4];
#pragma unroll
                for (int bn = 0; bn < 4; bn++)
                    ldmx4(bb[bn], smem_u32(&B[(bn * 16 + (lane & 7) + ((lane >> 4) << 3)) * AQS +
                                              kk * 16 + ((lane >> 3) & 1) * 8]));
#pragma unroll
                for (int nf = 0; nf < 8; nf++)
                    mma16816(O[nf], a, &bb[nf >> 1][(nf & 1) * 2]);
            }
        }
    }

    float il0 = (l0 > 0.f) ? 1.f / l0 : 0.f;
    float il1 = (l1 > 0.f) ? 1.f / l1 : 0.f;
#pragma unroll
    for (int nf = 0; nf < 8; nf++) {
        int c = hh * 64 + nf * 8 + (lane & 3) * 2;
        if (ra < NTOK) {
            long g = (long)(b * NTOK + ra) * DIM + c;
#pragma unroll
            for (int e = 0; e < 2; e++) {
                float v = O[nf][e] * il0;
                __nv_bfloat16 hb = __float2bfloat16(v);
                oh[g + e] = hb; ol[g + e] = __float2bfloat16(v - __bfloat162float(hb));
            }
        }
        if (rb < NTOK) {
            long g = (long)(b * NTOK + rb) * DIM + c;
#pragma unroll
            for (int e = 0; e < 2; e++) {
                float v = O[nf][2 + e] * il1;
                __nv_bfloat16 hb = __float2bfloat16(v);
                oh[g + e] = hb; ol[g + e] = __float2bfloat16(v - __bfloat162float(hb));
            }
        }
    }
}

// ---------------- fp32 -> bf16 hi/lo split ----------------
__global__ void split_kernel(const float* __restrict__ x, __nv_bfloat16* __restrict__ hi,
                             __nv_bfloat16* __restrict__ lo, long n) {
    long i = (long)blockIdx.x * 256 + threadIdx.x;
    if (i >= n) return;
    float v = x[i];
    __nv_bfloat16 h = __float2bfloat16(v);
    hi[i] = h;
    lo[i] = __float2bfloat16(v - __bfloat162float(h));
}

// ---------------- patch embed ----------------
__global__ void patch_embed_kernel(const float* __restrict__ x,
                                   const float* __restrict__ pw,
                                   const float* __restrict__ pb,
                                   const float* __restrict__ pos,
                                   float* __restrict__ t) {
    __shared__ float sp[768];
    int gx = blockIdx.x, gy = blockIdx.y, b = blockIdx.z;
    int tid = threadIdx.x;
    const float* xb = x + (long)b * 3 * 512 * 512;
    for (int e = tid; e < 768; e += 256) {
        int c = e >> 8, rem = e & 255, i = rem >> 4, j = rem & 15;
        sp[e] = xb[c * 262144 + (gy * 16 + i) * 512 + gx * 16 + j];
    }
    __syncthreads();
    int tok = gy * 32 + gx;
    for (int d = tid; d < 768; d += 256) {
        const float* wr = pw + (long)d * 768;
        float acc = 0.f;
#pragma unroll 8
        for (int k = 0; k < 768; k++) acc += wr[k] * sp[k];
        t[((long)(b * NTOK) + 1 + tok) * DIM + d] = acc + pb[d] + pos[(1 + tok) * DIM + d];
    }
}

__global__ void cls_kernel(const float* __restrict__ cls, const float* __restrict__ pos,
                           float* __restrict__ t) {
    int d = blockIdx.x * blockDim.x + threadIdx.x;
    if (d < DIM) {
        t[d] = cls[d] + pos[d];
        t[(long)NTOK * DIM + d] = cls[d] + pos[d];
    }
}

// ---------------- layernorm -> bf16 hi/lo ----------------
__global__ void ln_split_kernel(const float* __restrict__ x, const float* __restrict__ w,
                                const float* __restrict__ b,
                                __nv_bfloat16* __restrict__ yh, __nv_bfloat16* __restrict__ yl) {
    long row = blockIdx.x;
    const float* xr = x + row * DIM;
    int tid = threadIdx.x;
    float v0 = xr[tid], v1 = xr[tid + 256], v2 = xr[tid + 512];
    float s = v0 + v1 + v2;
    float sq = v0 * v0 + v1 * v1 + v2 * v2;
    __shared__ float rs[256], rq[256];
    rs[tid] = s; rq[tid] = sq;
    __syncthreads();
    for (int off = 128; off > 0; off >>= 1) {
        if (tid < off) { rs[tid] += rs[tid + off]; rq[tid] += rq[tid + off]; }
        __syncthreads();
    }
    __shared__ float mean_s, inv_s;
    if (tid == 0) {
        float m = rs[0] * (1.0f / 768.0f);
        float var = rq[0] * (1.0f / 768.0f) - m * m;
        mean_s = m;
        inv_s = rsqrtf(var + 1e-6f);
    }
    __syncthreads();
    float m = mean_s, inv = inv_s;
#pragma unroll
    for (int q = 0; q < 3; q++) {
        int c = tid + q * 256;
        float vv = (q == 0) ? v0 : (q == 1) ? v1 : v2;
        float v = (vv - m) * inv * w[c] + b[c];
        __nv_bfloat16 h = __float2bfloat16(v);
        yh[row * DIM + c] = h;
        yl[row * DIM + c] = __float2bfloat16(v - __bfloat162float(h));
    }
}

// ---------------- qkv bias assembly ----------------
__global__ void qkvbias_kernel(const float* __restrict__ qb, const float* __restrict__ vb,
                               float* __restrict__ ob) {
    int i = blockIdx.x * blockDim.x + threadIdx.x;
    if (i >= 3 * DIM) return;
    if (i < DIM) ob[i] = qb[i];
    else if (i < 2 * DIM) ob[i] = 0.f;
    else ob[i] = vb[i - 2 * DIM];
}

// ---------------- deconv weight transpose ----------------
__global__ void transw_kernel(const float* __restrict__ w, float* __restrict__ wt) {
    int idx = blockIdx.x * blockDim.x + threadIdx.x;
    if (idx >= 3072 * 768) return;
    int n = idx / 768, c = idx % 768;
    int dout = n % 768, ij = n / 768;
    wt[idx] = w[(long)c * 3072 + dout * 4 + ij];
}

// ---------------- fpn1 mid: +bias, BN, GELU -> channel-last bf16 hi/lo ----------------
__global__ void scatter_mid_kernel(const float* __restrict__ G, const float* __restrict__ bias,
                                   const float* __restrict__ bnw, const float* __restrict__ bnb,
                                   const float* __restrict__ bnm, const float* __restrict__ bnv,
                                   __nv_bfloat16* __restrict__ yh, __nv_bfloat16* __restrict__ yl) {
    int idx = blockIdx.x * blockDim.x + threadIdx.x;
    const int total = 2 * 1024 * 3072;
    if (idx >= total) return;
    int p = idx / 3072, n = idx % 3072;
    int b = p >> 10, hw = p & 1023, h = hw >> 5, wq = hw & 31;
    int ij = n / 768, dout = n % 768, i = ij >> 1, j = ij & 1;
    float val = G[idx] + bias[dout];
    val = (val - bnm[dout]) * rsqrtf(bnv[dout] + 1e-5f) * bnw[dout] + bnb[dout];
    val = gelu_exact(val);
    long o = (((long)b * 64 + (2 * h + i)) * 64 + (2 * wq + j)) * 768 + dout;
    __nv_bfloat16 hb = __float2bfloat16(val);
    yh[o] = hb; yl[o] = __float2bfloat16(val - __bfloat162float(hb));
}

__global__ void scatter_o1_kernel(const float* __restrict__ G, const float* __restrict__ bias,
                                  float* __restrict__ out) {
    int idx = blockIdx.x * blockDim.x + threadIdx.x;
    const int total = 8192 * 3072;
    if (idx >= total) return;
    int p = idx / 3072, n = idx % 3072;
    int b = p >> 12, yx = p & 4095, yy = yx >> 6, xx = yx & 63;
    int ij = n / 768, dout = n % 768, i = ij >> 1, j = ij & 1;
    float val = G[idx] + bias[dout];
    out[((long)(b * 768 + dout) << 14) + (2 * yy + i) * 128 + (2 * xx + j)] = val;
}

__global__ void scatter_o2_kernel(const float* __restrict__ G, const float* __restrict__ bias,
                                  float* __restrict__ out) {
    int idx = blockIdx.x * blockDim.x + threadIdx.x;
    const int total = 2 * 1024 * 3072;
    if (idx >= total) return;
    int p = idx / 3072, n = idx % 3072;
    int b = p >> 10, hw = p & 1023, h = hw >> 5, wq = hw & 31;
    int ij = n / 768, dout = n % 768, i = ij >> 1, j = ij & 1;
    float val = G[idx] + bias[dout];
    out[((long)(b * 768 + dout) << 12) + (2 * h + i) * 64 + (2 * wq + j)] = val;
}

__global__ void o3_kernel(const float* __restrict__ feat, float* __restrict__ out) {
    int idx = blockIdx.x * blockDim.x + threadIdx.x;
    const int total = 2 * 768 * 1024;
    if (idx >= total) return;
    int b = idx / (768 * 1024), rem = idx % (768 * 1024);
    int d = rem / 1024, yx = rem % 1024;
    out[idx] = feat[((long)b * NTOK + 1 + yx) * DIM + d];
}

__global__ void o4_kernel(const float* __restrict__ feat, float* __restrict__ out) {
    int idx = blockIdx.x * blockDim.x + threadIdx.x;
    const int total = 2 * 768 * 256;
    if (idx >= total) return;
    int b = idx / (768 * 256), rem = idx % (768 * 256);
    int d = rem / 256, hw = rem % 256;
    int h = hw >> 4, wq = hw & 15;
    float m = -1e30f;
#pragma unroll
    for (int i = 0; i < 2; i++)
#pragma unroll
        for (int j = 0; j < 2; j++) {
            int tok = 1 + (2 * h + i) * 32 + (2 * wq + j);
            float v = feat[((long)b * NTOK + tok) * DIM + d];
            m = fmaxf(m, v);
        }
    out[idx] = m;
}

// ---------------- host orchestration ----------------
extern "C" void kernel_launch(void* const* d_in, const int* in_sizes, int n_in,
                              void* d_out, int out_size) {
    const float* x        = (const float*)d_in[0];
    const float* patch_w  = (const float*)d_in[1];
    const float* patch_b  = (const float*)d_in[2];
    const float* cls_tok  = (const float*)d_in[3];
    const float* pos      = (const float*)d_in[4];
    const float* ln1_w    = (const float*)d_in[5];
    const float* ln1_b    = (const float*)d_in[6];
    const float* qkv_w    = (const float*)d_in[7];
    const float* q_bias   = (const float*)d_in[8];
    const float* v_bias   = (const float*)d_in[9];
    const float* rel_tab  = (const float*)d_in[10];
    const float* proj_w   = (const float*)d_in[11];
    const float* proj_b   = (const float*)d_in[12];
    const float* ln2_w    = (const float*)d_in[13];
    const float* ln2_b    = (const float*)d_in[14];
    const float* fc1_w    = (const float*)d_in[15];
    const float* fc1_b    = (const float*)d_in[16];
    const float* fc2_w    = (const float*)d_in[17];
    const float* fc2_b    = (const float*)d_in[18];
    const float* d1_w     = (const float*)d_in[19];
    const float* d1_b     = (const float*)d_in[20];
    const float* bn_w     = (const float*)d_in[21];
    const float* bn_b     = (const float*)d_in[22];
    const float* bn_mean  = (const float*)d_in[23];
    const float* bn_var   = (const float*)d_in[24];
    const float* d2_w     = (const float*)d_in[25];
    const float* d2_b     = (const float*)d_in[26];
    const float* f2_w     = (const float*)d_in[27];
    const float* f2_b     = (const float*)d_in[28];
    const int*   rel_idx  = (const int*)d_in[29];
    float* out = (float*)d_out;

    float *t_, *feats_, *qb_, *wt_, *gm_;
    __nv_bfloat16 *xh_, *xl_, *yh_, *yl_, *wh_, *wl_;
    cudaGetSymbolAddress((void**)&t_,    g_t);
    cudaGetSymbolAddress((void**)&feats_, g_feats);
    cudaGetSymbolAddress((void**)&qb_,   g_qkvbias);
    cudaGetSymbolAddress((void**)&wt_,   g_wt);
    cudaGetSymbolAddress((void**)&gm_,   g_gemm);
    cudaGetSymbolAddress((void**)&xh_,   g_xh);
    cudaGetSymbolAddress((void**)&xl_,   g_xl);
    cudaGetSymbolAddress((void**)&yh_,   g_yh);
    cudaGetSymbolAddress((void**)&yl_,   g_yl);
    cudaGetSymbolAddress((void**)&wh_,   g_wh);
    cudaGetSymbolAddress((void**)&wl_,   g_wl);

    cudaFuncSetAttribute(attn_mma_kernel, cudaFuncAttributeMaxDynamicSharedMemorySize, ATT_SMEM);

    patch_embed_kernel<<<dim3(32, 32, 2), 256>>>(x, patch_w, patch_b, pos, t_);
    cls_kernel<<<3, 256>>>(cls_tok, pos, t_);

    const int OUT_IDX[4] = {3, 5, 7, 11};
    int feat_k = 0;
    for (int l = 0; l < DEPTH; l++) {
        ln_split_kernel<<<BTOK, 256>>>(t_, ln1_w + l * DIM, ln1_b + l * DIM, xh_, xl_);
        qkvbias_kernel<<<9, 256>>>(q_bias + l * DIM, v_bias + l * DIM, qb_);
        split_kernel<<<(2304 * 768 + 255) / 256, 256>>>(qkv_w + (long)l * 2304 * 768, wh_, wl_,
                                                        2304L * 768);
        // QKV GEMM -> bf16 hi/lo directly
        gemm_mma_kernel<<<dim3(18, 17), 256>>>(xh_, xl_, wh_, wl_, qb_, nullptr,
                                               nullptr, yh_, yl_, BTOK, 2304, 768, 0);
        attn_mma_kernel<<<dim3(9, HEADS, 2), 256, ATT_SMEM>>>(
            yh_, yl_, rel_tab + (long)l * NUM_REL * HEADS, rel_idx, xh_, xl_);
        split_kernel<<<(768 * 768 + 255) / 256, 256>>>(proj_w + (long)l * 768 * 768, wh_, wl_,
                                                       768L * 768);
        gemm_mma_kernel<<<dim3(6, 17), 256>>>(xh_, xl_, wh_, wl_, proj_b + l * DIM, t_,
                                              t_, nullptr, nullptr, BTOK, 768, 768, 0);
        ln_split_kernel<<<BTOK, 256>>>(t_, ln2_w + l * DIM, ln2_b + l * DIM, xh_, xl_);
        split_kernel<<<(3072 * 768 + 255) / 256, 256>>>(fc1_w + (long)l * 3072 * 768, wh_, wl_,
                                                        3072L * 768);
        gemm_mma_kernel<<<dim3(24, 17), 256>>>(xh_, xl_, wh_, wl_, fc1_b + l * 3072,
                                               nullptr, nullptr, yh_, yl_, BTOK, 3072, 768, 1);
        split_kernel<<<(768 * 3072 + 255) / 256, 256>>>(fc2_w + (long)l * 768 * 3072, wh_, wl_,
                                                        768L * 3072);
        gemm_mma_kernel<<<dim3(6, 17), 256>>>(yh_, yl_, wh_, wl_, fc2_b + l * DIM, t_,
                                              t_, nullptr, nullptr, BTOK, 768, 3072, 0);
        if (feat_k < 4 && l == OUT_IDX[feat_k]) {
            cudaMemcpyAsync(feats_ + (long)feat_k * FEAT, t_, (long)FEAT * sizeof(float),
                            cudaMemcpyDeviceToDevice);
            feat_k++;
        }
    }

    const long O1 = 2L * 768 * 128 * 128;
    const long O2 = 2L * 768 * 64 * 64;
    const long O3 = 2L * 768 * 32 * 32;

    // fpn1 stage A: deconv d1 on feats[0]
    transw_kernel<<<(3072 * 768 + 255) / 256, 256>>>(d1_w, wt_);
    split_kernel<<<(3072 * 768 + 255) / 256, 256>>>(wt_, wh_, wl_, 3072L * 768);
    for (int b = 0; b < 2; b++) {
        split_kernel<<<(1024 * 768 + 255) / 256, 256>>>(
            feats_ + 0L * FEAT + (long)b * NTOK * DIM + DIM, xh_, xl_, 1024L * 768);
        gemm_mma_kernel<<<dim3(24, 8), 256>>>(xh_, xl_, wh_, wl_, nullptr, nullptr,
                                              gm_ + (long)b * 1024 * 3072, nullptr, nullptr,
                                              1024, 3072, 768, 0);
    }
    scatter_mid_kernel<<<(2 * 1024 * 3072 + 255) / 256, 256>>>(gm_, d1_b, bn_w, bn_b,
                                                               bn_mean, bn_var, yh_, yl_);
    // fpn1 stage B: deconv d2 -> o1
    transw_kernel<<<(3072 * 768 + 255) / 256, 256>>>(d2_w, wt_);
    split_kernel<<<(3072 * 768 + 255) / 256, 256>>>(wt_, wh_, wl_, 3072L * 768);
    gemm_mma_kernel<<<dim3(24, 64), 256>>>(yh_, yl_, wh_, wl_, nullptr, nullptr,
                                           gm_, nullptr, nullptr, 8192, 3072, 768, 0);
    scatter_o1_kernel<<<(8192 * 3072 + 255) / 256, 256>>>(gm_, d2_b, out);

    // fpn2: deconv f2 on feats[1] -> o2
    transw_kernel<<<(3072 * 768 + 255) / 256, 256>>>(f2_w, wt_);
    split_kernel<<<(3072 * 768 + 255) / 256, 256>>>(wt_, wh_, wl_, 3072L * 768);
    for (int b = 0; b < 2; b++) {
        split_kernel<<<(1024 * 768 + 255) / 256, 256>>>(
            feats_ + 1L * FEAT + (long)b * NTOK * DIM + DIM, xh_, xl_, 1024L * 768);
        gemm_mma_kernel<<<dim3(24, 8), 256>>>(xh_, xl_, wh_, wl_, nullptr, nullptr,
                                              gm_ + (long)b * 1024 * 3072, nullptr, nullptr,
                                              1024, 3072, 768, 0);
    }
    scatter_o2_kernel<<<(2 * 1024 * 3072 + 255) / 256, 256>>>(gm_, f2_b, out + O1);

    o3_kernel<<<(2 * 768 * 1024 + 255) / 256, 256>>>(feats_ + 2L * FEAT, out + O1 + O2);
    o4_kernel<<<(2 * 768 * 256 + 255) / 256, 256>>>(feats_ + 3L * FEAT, out + O1 + O2 + O3);
}

// round 9
// speedup vs baseline: 1.7042x; 1.1336x over previous
#include <cuda_runtime.h>
#include <cuda_bf16.h>
#include <math.h>
#include <stdint.h>

#define DEPTH 12
#define HEADS 12
#define DIM 768
#define NTOK 1025
#define NUM_REL 3972
#define BTOK (2 * NTOK)            // 2050 rows
#define FEAT (2 * NTOK * DIM)      // per-feat floats

// ---------------- scratch (static device globals; no allocation) ----------------
__device__ float g_t[FEAT];
__device__ float g_feats[4 * FEAT];
__device__ float g_qkvbias[3 * DIM];
__device__ float g_wt[4 * DIM * DIM];              // transposed deconv weight fp32
__device__ float g_gemm[8192 * 3072];              // deconv GEMM fp32 out
// bf16 hi/lo operand buffers
__device__ __nv_bfloat16 g_xh[BTOK * DIM];
__device__ __nv_bfloat16 g_xl[BTOK * DIM];
__device__ __nv_bfloat16 g_yh[2050 * 3072];
__device__ __nv_bfloat16 g_yl[2050 * 3072];
__device__ __nv_bfloat16 g_wh[3072 * 768];
__device__ __nv_bfloat16 g_wl[3072 * 768];

__device__ __forceinline__ float gelu_exact(float x) {
    return 0.5f * x * (1.0f + erff(x * 0.70710678118654752f));
}

__device__ __forceinline__ uint32_t smem_u32(const void* p) {
    uint32_t a;
    asm("{ .reg .u64 tmp; cvta.to.shared.u64 tmp, %1; cvt.u32.u64 %0, tmp; }"
        : "=r"(a) : "l"(p));
    return a;
}

__device__ __forceinline__ void ldmx4(uint32_t* r, uint32_t addr) {
    asm volatile("ldmatrix.sync.aligned.m8n8.x4.shared.b16 {%0,%1,%2,%3}, [%4];"
                 : "=r"(r[0]), "=r"(r[1]), "=r"(r[2]), "=r"(r[3]) : "r"(addr));
}

__device__ __forceinline__ void mma16816(float* d, const uint32_t* a, const uint32_t* b) {
    asm volatile(
        "mma.sync.aligned.m16n8k16.row.col.f32.bf16.bf16.f32 "
        "{%0,%1,%2,%3}, {%4,%5,%6,%7}, {%8,%9}, {%0,%1,%2,%3};"
        : "+f"(d[0]), "+f"(d[1]), "+f"(d[2]), "+f"(d[3])
        : "r"(a[0]), "r"(a[1]), "r"(a[2]), "r"(a[3]), "r"(b[0]), "r"(b[1]));
}

__device__ __forceinline__ void cp_async16(uint32_t dst, const void* src, int sz) {
    asm volatile("cp.async.cg.shared.global [%0], [%1], 16, %2;"
                 :: "r"(dst), "l"(src), "r"(sz));
}
__device__ __forceinline__ void cp_commit() {
    asm volatile("cp.async.commit_group;" ::: "memory");
}
template <int N>
__device__ __forceinline__ void cp_wait() {
    asm volatile("cp.async.wait_group %0;" :: "n"(N) : "memory");
}

// ---------------- HMMA GEMM: C = (Ah+Al)(Bh+Bl)^T via 3 bf16 passes ----------------
// 4-stage cp.async pipeline; 128x128 tile, BK=32.
#define LDT 40                       // smem row stride in bf16 (32 data + 8 pad)
#define GEMM_STAGES 4
#define GEMM_CH (128 * LDT)          // elements per A or B tile buffer
#define GEMM_SMEM (GEMM_STAGES * 2 * GEMM_CH * 2)   // 81920 bytes

__global__ void __launch_bounds__(256) gemm_mma_kernel(
    const __nv_bfloat16* __restrict__ Ah, const __nv_bfloat16* __restrict__ Al,
    const __nv_bfloat16* __restrict__ Bh, const __nv_bfloat16* __restrict__ Bl,
    const float* __restrict__ bias, const float* __restrict__ res,
    float* __restrict__ C, __nv_bfloat16* __restrict__ Ch, __nv_bfloat16* __restrict__ Cl,
    int M, int N, int K, int act) {
    extern __shared__ __nv_bfloat16 dsm[];
    int t = threadIdx.x, wid = t >> 5, lane = t & 31;
    int row0 = blockIdx.y * 128, col0 = blockIdx.x * 128;
    int m0 = (wid >> 1) * 32, n0 = (wid & 1) * 64;

    float acc[2][8][4];
#pragma unroll
    for (int i = 0; i < 2; i++)
#pragma unroll
        for (int j = 0; j < 8; j++)
#pragma unroll
            for (int c = 0; c < 4; c++) acc[i][j][c] = 0.f;

    const int KC = K >> 5;
    const int NC = 3 * KC;

    auto load_chunk = [&](int s, int i) {
        int p = i / KC, kc = i - p * KC;
        const __nv_bfloat16* As = (p < 2) ? Ah : Al;
        const __nv_bfloat16* Bs = (p == 1) ? Bl : Bh;
        long kb = (long)kc * 32;
        __nv_bfloat16* dA = dsm + s * 2 * GEMM_CH;
        __nv_bfloat16* dB = dA + GEMM_CH;
#pragma unroll
        for (int u = 0; u < 2; u++) {
            int unit = t + u * 256;
            int r = unit >> 2, seg = unit & 3;
            int gr = row0 + r;
            const __nv_bfloat16* src = As + (long)(gr < M ? gr : 0) * K + kb + seg * 8;
            cp_async16(smem_u32(&dA[r * LDT + seg * 8]), src, (gr < M) ? 16 : 0);
        }
#pragma unroll
        for (int u = 0; u < 2; u++) {
            int unit = t + u * 256;
            int r = unit >> 2, seg = unit & 3;
            cp_async16(smem_u32(&dB[r * LDT + seg * 8]),
                       Bs + (long)(col0 + r) * K + kb + seg * 8, 16);
        }
        cp_commit();
    };

    // prologue: fill STAGES-1 stages
#pragma unroll
    for (int s = 0; s < GEMM_STAGES - 1; s++) {
        if (s < NC) load_chunk(s, s);
        else cp_commit();
    }

    for (int i = 0; i < NC; i++) {
        cp_wait<GEMM_STAGES - 2>();
        __syncthreads();
        // issue next loads before consuming this stage (max overlap)
        if (i + GEMM_STAGES - 1 < NC)
            load_chunk((i + GEMM_STAGES - 1) % GEMM_STAGES, i + GEMM_STAGES - 1);
        else
            cp_commit();

        int cur = i % GEMM_STAGES;
        const __nv_bfloat16* sAc = dsm + cur * 2 * GEMM_CH;
        const __nv_bfloat16* sBc = sAc + GEMM_CH;
#pragma unroll
        for (int ks = 0; ks < 2; ks++) {
            int kst = ks * 16;
            uint32_t a[2][4];
#pragma unroll
            for (int am = 0; am < 2; am++) {
                int r = m0 + am * 16 + (lane & 15);
                int kc2 = kst + (lane >> 4) * 8;
                ldmx4(a[am], smem_u32(&sAc[r * LDT + kc2]));
            }
            uint32_t b[4][4];
#pragma unroll
            for (int bn = 0; bn < 4; bn++) {
                int r = n0 + bn * 16 + (lane & 7) + ((lane >> 4) << 3);
                int kc2 = kst + ((lane >> 3) & 1) * 8;
                ldmx4(b[bn], smem_u32(&sBc[r * LDT + kc2]));
            }
#pragma unroll
            for (int am = 0; am < 2; am++)
#pragma unroll
                for (int nn = 0; nn < 8; nn++)
                    mma16816(acc[am][nn], a[am], &b[nn >> 1][(nn & 1) * 2]);
        }
        __syncthreads();
    }

#pragma unroll
    for (int am = 0; am < 2; am++) {
        int rb = row0 + m0 + am * 16 + (lane >> 2);
#pragma unroll
        for (int half = 0; half < 2; half++) {
            int r = rb + half * 8;
            if (r >= M) continue;
#pragma unroll
            for (int nn = 0; nn < 8; nn++) {
                int col = col0 + n0 + nn * 8 + (lane & 3) * 2;
                long base = (long)r * N + col;
#pragma unroll
                for (int e = 0; e < 2; e++) {
                    float v = acc[am][nn][half * 2 + e];
                    int n = col + e;
                    if (bias) v += bias[n];
                    if (res)  v += res[base + e];
                    if (act)  v = gelu_exact(v);
                    if (C)    C[base + e] = v;
                    if (Ch) {
                        __nv_bfloat16 hb = __float2bfloat16(v);
                        Ch[base + e] = hb;
                        Cl[base + e] = __float2bfloat16(v - __bfloat162float(hb));
                    }
                }
            }
        }
    }
}

// ---------------- flash HMMA attention ----------------
#define AQS 72
#define ATT_SMEM (55296 * 2)   // bytes

__global__ void __launch_bounds__(256) attn_mma_kernel(
    const __nv_bfloat16* __restrict__ qh, const __nv_bfloat16* __restrict__ ql,
    const float* __restrict__ relT, const int* __restrict__ relIdx,
    __nv_bfloat16* __restrict__ oh, __nv_bfloat16* __restrict__ ol) {
    extern __shared__ __nv_bfloat16 sm[];
    __nv_bfloat16 *sQh = sm,          *sQl = sm + 9216;
    __nv_bfloat16 *sKh = sm + 18432,  *sKl = sm + 23040;
    __nv_bfloat16 *sVh = sm + 27648,  *sVl = sm + 32256;
    __nv_bfloat16 *sPh = sm + 36864,  *sPl = sm + 46080;
    int t = threadIdx.x, w = t >> 5, lane = t & 31;
    int it = blockIdx.x, hh = blockIdx.y, b = blockIdx.z;
    int i0 = it * 128;
    const int LD3 = 3 * DIM;

    for (int idx = t; idx < 128 * 64; idx += 256) {
        int r = idx >> 6, d = idx & 63;
        int i = i0 + r;
        float vh = 0.f, vl = 0.f;
        if (i < NTOK) {
            long g = (long)(b * NTOK + i) * LD3 + hh * 64 + d;
            vh = __bfloat162float(qh[g]); vl = __bfloat162float(ql[g]);
        }
        sQh[r * AQS + d] = __float2bfloat16(vh * 0.125f);
        sQl[r * AQS + d] = __float2bfloat16(vl * 0.125f);
    }

    float m0 = -1e30f, m1 = -1e30f, l0 = 0.f, l1 = 0.f;
    float O[8][4];
#pragma unroll
    for (int nf = 0; nf < 8; nf++)
#pragma unroll
        for (int e = 0; e < 4; e++) O[nf][e] = 0.f;

    int ra = i0 + w * 16 + (lane >> 2);
    int rb = ra + 8;

    for (int jt = 0; jt < 17; jt++) {
        int j0 = jt * 64;
        __syncthreads();
        for (int idx = t; idx < 64 * 64; idx += 256) {
            int r = idx >> 6, d = idx & 63;
            int j = j0 + r;
            __nv_bfloat16 kh = __float2bfloat16(0.f), kl = kh;
            if (j < NTOK) {
                long g = (long)(b * NTOK + j) * LD3 + DIM + hh * 64 + d;
                kh = qh[g]; kl = ql[g];
            }
            sKh[r * AQS + d] = kh; sKl[r * AQS + d] = kl;
        }
        for (int idx = t; idx < 64 * 64; idx += 256) {
            int j = idx >> 6, d = idx & 63;
            int jg = j0 + j;
            __nv_bfloat16 vh = __float2bfloat16(0.f), vl = vh;
            if (jg < NTOK) {
                long g = (long)(b * NTOK + jg) * LD3 + 2 * DIM + hh * 64 + d;
                vh = qh[g]; vl = ql[g];
            }
            sVh[d * AQS + j] = vh; sVl[d * AQS + j] = vl;
        }
        __syncthreads();

        float S[8][4];
#pragma unroll
        for (int nf = 0; nf < 8; nf++)
#pragma unroll
            for (int e = 0; e < 4; e++) S[nf][e] = 0.f;
#pragma unroll
        for (int p = 0; p < 3; p++) {
            const __nv_bfloat16* A = (p < 2) ? sQh : sQl;
            const __nv_bfloat16* B = (p == 1) ? sKl : sKh;
#pragma unroll
            for (int kk = 0; kk < 4; kk++) {
                uint32_t a[4];
                ldmx4(a, smem_u32(&A[(w * 16 + (lane & 15)) * AQS + kk * 16 + (lane >> 4) * 8]));
                uint32_t bb[4][4];
#pragma unroll
                for (int bn = 0; bn < 4; bn++)
                    ldmx4(bb[bn], smem_u32(&B[(bn * 16 + (lane & 7) + ((lane >> 4) << 3)) * AQS +
                                              kk * 16 + ((lane >> 3) & 1) * 8]));
#pragma unroll
                for (int nf = 0; nf < 8; nf++)
                    mma16816(S[nf], a, &bb[nf >> 1][(nf & 1) * 2]);
            }
        }

#pragma unroll
        for (int nf = 0; nf < 8; nf++) {
#pragma unroll
            for (int e = 0; e < 2; e++) {
                int c = j0 + nf * 8 + (lane & 3) * 2 + e;
                if (ra <= 1024 && c <= 1024)
                    S[nf][e] += relT[(long)relIdx[(long)ra * NTOK + c] * HEADS + hh];
                else S[nf][e] = -1e30f;
                if (rb <= 1024 && c <= 1024)
                    S[nf][2 + e] += relT[(long)relIdx[(long)rb * NTOK + c] * HEADS + hh];
                else S[nf][2 + e] = -1e30f;
            }
        }

        float mx0 = -1e30f, mx1 = -1e30f;
#pragma unroll
        for (int nf = 0; nf < 8; nf++) {
            mx0 = fmaxf(mx0, fmaxf(S[nf][0], S[nf][1]));
            mx1 = fmaxf(mx1, fmaxf(S[nf][2], S[nf][3]));
        }
        mx0 = fmaxf(mx0, __shfl_xor_sync(0xffffffff, mx0, 1));
        mx0 = fmaxf(mx0, __shfl_xor_sync(0xffffffff, mx0, 2));
        mx1 = fmaxf(mx1, __shfl_xor_sync(0xffffffff, mx1, 1));
        mx1 = fmaxf(mx1, __shfl_xor_sync(0xffffffff, mx1, 2));
        float nm0 = fmaxf(m0, mx0), nm1 = fmaxf(m1, mx1);
        float al0 = __expf(m0 - nm0), al1 = __expf(m1 - nm1);
        float s0 = 0.f, s1 = 0.f;
        int pr0 = w * 16 + (lane >> 2), pr1 = pr0 + 8;
#pragma unroll
        for (int nf = 0; nf < 8; nf++) {
#pragma unroll
            for (int e = 0; e < 2; e++) {
                int cl = nf * 8 + (lane & 3) * 2 + e;
                float p0 = __expf(S[nf][e] - nm0);
                s0 += p0;
                __nv_bfloat16 h0 = __float2bfloat16(p0);
                sPh[pr0 * AQS + cl] = h0;
                sPl[pr0 * AQS + cl] = __float2bfloat16(p0 - __bfloat162float(h0));
                float p1 = __expf(S[nf][2 + e] - nm1);
                s1 += p1;
                __nv_bfloat16 h1 = __float2bfloat16(p1);
                sPh[pr1 * AQS + cl] = h1;
                sPl[pr1 * AQS + cl] = __float2bfloat16(p1 - __bfloat162float(h1));
            }
        }
        s0 += __shfl_xor_sync(0xffffffff, s0, 1);
        s0 += __shfl_xor_sync(0xffffffff, s0, 2);
        s1 += __shfl_xor_sync(0xffffffff, s1, 1);
        s1 += __shfl_xor_sync(0xffffffff, s1, 2);
        l0 = l0 * al0 + s0; l1 = l1 * al1 + s1;
        m0 = nm0; m1 = nm1;
#pragma unroll
        for (int nf = 0; nf < 8; nf++) {
            O[nf][0] *= al0; O[nf][1] *= al0;
            O[nf][2] *= al1; O[nf][3] *= al1;
        }
        __syncthreads();

#pragma unroll
        for (int p = 0; p < 3; p++) {
            const __nv_bfloat16* A = (p < 2) ? sPh : sPl;
            const __nv_bfloat16* B = (p == 1) ? sVl : sVh;
#pragma unroll
            for (int kk = 0; kk < 4; kk++) {
                uint32_t a[4];
                ldmx4(a, smem_u32(&A[(w * 16 + (lane & 15)) * AQS + kk * 16 + (lane >> 4) * 8]));
                uint32_t bb[4][4];
#pragma unroll
                for (int bn = 0; bn < 4; bn++)
                    ldmx4(bb[bn], smem_u32(&B[(bn * 16 + (lane & 7) + ((lane >> 4) << 3)) * AQS +
                                              kk * 16 + ((lane >> 3) & 1) * 8]));
#pragma unroll
                for (int nf = 0; nf < 8; nf++)
                    mma16816(O[nf], a, &bb[nf >> 1][(nf & 1) * 2]);
            }
        }
    }

    float il0 = (l0 > 0.f) ? 1.f / l0 : 0.f;
    float il1 = (l1 > 0.f) ? 1.f / l1 : 0.f;
#pragma unroll
    for (int nf = 0; nf < 8; nf++) {
        int c = hh * 64 + nf * 8 + (lane & 3) * 2;
        if (ra < NTOK) {
            long g = (long)(b * NTOK + ra) * DIM + c;
#pragma unroll
            for (int e = 0; e < 2; e++) {
                float v = O[nf][e] * il0;
                __nv_bfloat16 hb = __float2bfloat16(v);
                oh[g + e] = hb; ol[g + e] = __float2bfloat16(v - __bfloat162float(hb));
            }
        }
        if (rb < NTOK) {
            long g = (long)(b * NTOK + rb) * DIM + c;
#pragma unroll
            for (int e = 0; e < 2; e++) {
                float v = O[nf][2 + e] * il1;
                __nv_bfloat16 hb = __float2bfloat16(v);
                oh[g + e] = hb; ol[g + e] = __float2bfloat16(v - __bfloat162float(hb));
            }
        }
    }
}

// ---------------- fp32 -> bf16 hi/lo split ----------------
__global__ void split_kernel(const float* __restrict__ x, __nv_bfloat16* __restrict__ hi,
                             __nv_bfloat16* __restrict__ lo, long n) {
    long i = (long)blockIdx.x * 256 + threadIdx.x;
    if (i >= n) return;
    float v = x[i];
    __nv_bfloat16 h = __float2bfloat16(v);
    hi[i] = h;
    lo[i] = __float2bfloat16(v - __bfloat162float(h));
}

// ---------------- patch embed ----------------
__global__ void patch_embed_kernel(const float* __restrict__ x,
                                   const float* __restrict__ pw,
                                   const float* __restrict__ pb,
                                   const float* __restrict__ pos,
                                   float* __restrict__ t) {
    __shared__ float sp[768];
    int gx = blockIdx.x, gy = blockIdx.y, b = blockIdx.z;
    int tid = threadIdx.x;
    const float* xb = x + (long)b * 3 * 512 * 512;
    for (int e = tid; e < 768; e += 256) {
        int c = e >> 8, rem = e & 255, i = rem >> 4, j = rem & 15;
        sp[e] = xb[c * 262144 + (gy * 16 + i) * 512 + gx * 16 + j];
    }
    __syncthreads();
    int tok = gy * 32 + gx;
    for (int d = tid; d < 768; d += 256) {
        const float* wr = pw + (long)d * 768;
        float acc = 0.f;
#pragma unroll 8
        for (int k = 0; k < 768; k++) acc += wr[k] * sp[k];
        t[((long)(b * NTOK) + 1 + tok) * DIM + d] = acc + pb[d] + pos[(1 + tok) * DIM + d];
    }
}

__global__ void cls_kernel(const float* __restrict__ cls, const float* __restrict__ pos,
                           float* __restrict__ t) {
    int d = blockIdx.x * blockDim.x + threadIdx.x;
    if (d < DIM) {
        t[d] = cls[d] + pos[d];
        t[(long)NTOK * DIM + d] = cls[d] + pos[d];
    }
}

// ---------------- layernorm -> bf16 hi/lo ----------------
__global__ void ln_split_kernel(const float* __restrict__ x, const float* __restrict__ w,
                                const float* __restrict__ b,
                                __nv_bfloat16* __restrict__ yh, __nv_bfloat16* __restrict__ yl) {
    long row = blockIdx.x;
    const float* xr = x + row * DIM;
    int tid = threadIdx.x;
    float v0 = xr[tid], v1 = xr[tid + 256], v2 = xr[tid + 512];
    float s = v0 + v1 + v2;
    float sq = v0 * v0 + v1 * v1 + v2 * v2;
    __shared__ float rs[256], rq[256];
    rs[tid] = s; rq[tid] = sq;
    __syncthreads();
    for (int off = 128; off > 0; off >>= 1) {
        if (tid < off) { rs[tid] += rs[tid + off]; rq[tid] += rq[tid + off]; }
        __syncthreads();
    }
    __shared__ float mean_s, inv_s;
    if (tid == 0) {
        float m = rs[0] * (1.0f / 768.0f);
        float var = rq[0] * (1.0f / 768.0f) - m * m;
        mean_s = m;
        inv_s = rsqrtf(var + 1e-6f);
    }
    __syncthreads();
    float m = mean_s, inv = inv_s;
#pragma unroll
    for (int q = 0; q < 3; q++) {
        int c = tid + q * 256;
        float vv = (q == 0) ? v0 : (q == 1) ? v1 : v2;
        float v = (vv - m) * inv * w[c] + b[c];
        __nv_bfloat16 h = __float2bfloat16(v);
        yh[row * DIM + c] = h;
        yl[row * DIM + c] = __float2bfloat16(v - __bfloat162float(h));
    }
}

// ---------------- qkv bias assembly ----------------
__global__ void qkvbias_kernel(const float* __restrict__ qb, const float* __restrict__ vb,
                               float* __restrict__ ob) {
    int i = blockIdx.x * blockDim.x + threadIdx.x;
    if (i >= 3 * DIM) return;
    if (i < DIM) ob[i] = qb[i];
    else if (i < 2 * DIM) ob[i] = 0.f;
    else ob[i] = vb[i - 2 * DIM];
}

// ---------------- deconv weight transpose ----------------
__global__ void transw_kernel(const float* __restrict__ w, float* __restrict__ wt) {
    int idx = blockIdx.x * blockDim.x + threadIdx.x;
    if (idx >= 3072 * 768) return;
    int n = idx / 768, c = idx % 768;
    int dout = n % 768, ij = n / 768;
    wt[idx] = w[(long)c * 3072 + dout * 4 + ij];
}

// ---------------- fpn1 mid: +bias, BN, GELU -> channel-last bf16 hi/lo ----------------
__global__ void scatter_mid_kernel(const float* __restrict__ G, const float* __restrict__ bias,
                                   const float* __restrict__ bnw, const float* __restrict__ bnb,
                                   const float* __restrict__ bnm, const float* __restrict__ bnv,
                                   __nv_bfloat16* __restrict__ yh, __nv_bfloat16* __restrict__ yl) {
    int idx = blockIdx.x * blockDim.x + threadIdx.x;
    const int total = 2 * 1024 * 3072;
    if (idx >= total) return;
    int p = idx / 3072, n = idx % 3072;
    int b = p >> 10, hw = p & 1023, h = hw >> 5, wq = hw & 31;
    int ij = n / 768, dout = n % 768, i = ij >> 1, j = ij & 1;
    float val = G[idx] + bias[dout];
    val = (val - bnm[dout]) * rsqrtf(bnv[dout] + 1e-5f) * bnw[dout] + bnb[dout];
    val = gelu_exact(val);
    long o = (((long)b * 64 + (2 * h + i)) * 64 + (2 * wq + j)) * 768 + dout;
    __nv_bfloat16 hb = __float2bfloat16(val);
    yh[o] = hb; yl[o] = __float2bfloat16(val - __bfloat162float(hb));
}

__global__ void scatter_o1_kernel(const float* __restrict__ G, const float* __restrict__ bias,
                                  float* __restrict__ out) {
    int idx = blockIdx.x * blockDim.x + threadIdx.x;
    const int total = 8192 * 3072;
    if (idx >= total) return;
    int p = idx / 3072, n = idx % 3072;
    int b = p >> 12, yx = p & 4095, yy = yx >> 6, xx = yx & 63;
    int ij = n / 768, dout = n % 768, i = ij >> 1, j = ij & 1;
    float val = G[idx] + bias[dout];
    out[((long)(b * 768 + dout) << 14) + (2 * yy + i) * 128 + (2 * xx + j)] = val;
}

__global__ void scatter_o2_kernel(const float* __restrict__ G, const float* __restrict__ bias,
                                  float* __restrict__ out) {
    int idx = blockIdx.x * blockDim.x + threadIdx.x;
    const int total = 2 * 1024 * 3072;
    if (idx >= total) return;
    int p = idx / 3072, n = idx % 3072;
    int b = p >> 10, hw = p & 1023, h = hw >> 5, wq = hw & 31;
    int ij = n / 768, dout = n % 768, i = ij >> 1, j = ij & 1;
    float val = G[idx] + bias[dout];
    out[((long)(b * 768 + dout) << 12) + (2 * h + i) * 64 + (2 * wq + j)] = val;
}

__global__ void o3_kernel(const float* __restrict__ feat, float* __restrict__ out) {
    int idx = blockIdx.x * blockDim.x + threadIdx.x;
    const int total = 2 * 768 * 1024;
    if (idx >= total) return;
    int b = idx / (768 * 1024), rem = idx % (768 * 1024);
    int d = rem / 1024, yx = rem % 1024;
    out[idx] = feat[((long)b * NTOK + 1 + yx) * DIM + d];
}

__global__ void o4_kernel(const float* __restrict__ feat, float* __restrict__ out) {
    int idx = blockIdx.x * blockDim.x + threadIdx.x;
    const int total = 2 * 768 * 256;
    if (idx >= total) return;
    int b = idx / (768 * 256), rem = idx % (768 * 256);
    int d = rem / 256, hw = rem % 256;
    int h = hw >> 4, wq = hw & 15;
    float m = -1e30f;
#pragma unroll
    for (int i = 0; i < 2; i++)
#pragma unroll
        for (int j = 0; j < 2; j++) {
            int tok = 1 + (2 * h + i) * 32 + (2 * wq + j);
            float v = feat[((long)b * NTOK + tok) * DIM + d];
            m = fmaxf(m, v);
        }
    out[idx] = m;
}

// ---------------- host orchestration ----------------
extern "C" void kernel_launch(void* const* d_in, const int* in_sizes, int n_in,
                              void* d_out, int out_size) {
    const float* x        = (const float*)d_in[0];
    const float* patch_w  = (const float*)d_in[1];
    const float* patch_b  = (const float*)d_in[2];
    const float* cls_tok  = (const float*)d_in[3];
    const float* pos      = (const float*)d_in[4];
    const float* ln1_w    = (const float*)d_in[5];
    const float* ln1_b    = (const float*)d_in[6];
    const float* qkv_w    = (const float*)d_in[7];
    const float* q_bias   = (const float*)d_in[8];
    const float* v_bias   = (const float*)d_in[9];
    const float* rel_tab  = (const float*)d_in[10];
    const float* proj_w   = (const float*)d_in[11];
    const float* proj_b   = (const float*)d_in[12];
    const float* ln2_w    = (const float*)d_in[13];
    const float* ln2_b    = (const float*)d_in[14];
    const float* fc1_w    = (const float*)d_in[15];
    const float* fc1_b    = (const float*)d_in[16];
    const float* fc2_w    = (const float*)d_in[17];
    const float* fc2_b    = (const float*)d_in[18];
    const float* d1_w     = (const float*)d_in[19];
    const float* d1_b     = (const float*)d_in[20];
    const float* bn_w     = (const float*)d_in[21];
    const float* bn_b     = (const float*)d_in[22];
    const float* bn_mean  = (const float*)d_in[23];
    const float* bn_var   = (const float*)d_in[24];
    const float* d2_w     = (const float*)d_in[25];
    const float* d2_b     = (const float*)d_in[26];
    const float* f2_w     = (const float*)d_in[27];
    const float* f2_b     = (const float*)d_in[28];
    const int*   rel_idx  = (const int*)d_in[29];
    float* out = (float*)d_out;

    float *t_, *feats_, *qb_, *wt_, *gm_;
    __nv_bfloat16 *xh_, *xl_, *yh_, *yl_, *wh_, *wl_;
    cudaGetSymbolAddress((void**)&t_,    g_t);
    cudaGetSymbolAddress((void**)&feats_, g_feats);
    cudaGetSymbolAddress((void**)&qb_,   g_qkvbias);
    cudaGetSymbolAddress((void**)&wt_,   g_wt);
    cudaGetSymbolAddress((void**)&gm_,   g_gemm);
    cudaGetSymbolAddress((void**)&xh_,   g_xh);
    cudaGetSymbolAddress((void**)&xl_,   g_xl);
    cudaGetSymbolAddress((void**)&yh_,   g_yh);
    cudaGetSymbolAddress((void**)&yl_,   g_yl);
    cudaGetSymbolAddress((void**)&wh_,   g_wh);
    cudaGetSymbolAddress((void**)&wl_,   g_wl);

    cudaFuncSetAttribute(attn_mma_kernel, cudaFuncAttributeMaxDynamicSharedMemorySize, ATT_SMEM);
    cudaFuncSetAttribute(gemm_mma_kernel, cudaFuncAttributeMaxDynamicSharedMemorySize, GEMM_SMEM);

    patch_embed_kernel<<<dim3(32, 32, 2), 256>>>(x, patch_w, patch_b, pos, t_);
    cls_kernel<<<3, 256>>>(cls_tok, pos, t_);

    const int OUT_IDX[4] = {3, 5, 7, 11};
    int feat_k = 0;
    for (int l = 0; l < DEPTH; l++) {
        ln_split_kernel<<<BTOK, 256>>>(t_, ln1_w + l * DIM, ln1_b + l * DIM, xh_, xl_);
        qkvbias_kernel<<<9, 256>>>(q_bias + l * DIM, v_bias + l * DIM, qb_);
        split_kernel<<<(2304 * 768 + 255) / 256, 256>>>(qkv_w + (long)l * 2304 * 768, wh_, wl_,
                                                        2304L * 768);
        gemm_mma_kernel<<<dim3(18, 17), 256, GEMM_SMEM>>>(xh_, xl_, wh_, wl_, qb_, nullptr,
                                                          nullptr, yh_, yl_, BTOK, 2304, 768, 0);
        attn_mma_kernel<<<dim3(9, HEADS, 2), 256, ATT_SMEM>>>(
            yh_, yl_, rel_tab + (long)l * NUM_REL * HEADS, rel_idx, xh_, xl_);
        split_kernel<<<(768 * 768 + 255) / 256, 256>>>(proj_w + (long)l * 768 * 768, wh_, wl_,
                                                       768L * 768);
        gemm_mma_kernel<<<dim3(6, 17), 256, GEMM_SMEM>>>(xh_, xl_, wh_, wl_, proj_b + l * DIM, t_,
                                                         t_, nullptr, nullptr, BTOK, 768, 768, 0);
        ln_split_kernel<<<BTOK, 256>>>(t_, ln2_w + l * DIM, ln2_b + l * DIM, xh_, xl_);
        split_kernel<<<(3072 * 768 + 255) / 256, 256>>>(fc1_w + (long)l * 3072 * 768, wh_, wl_,
                                                        3072L * 768);
        gemm_mma_kernel<<<dim3(24, 17), 256, GEMM_SMEM>>>(xh_, xl_, wh_, wl_, fc1_b + l * 3072,
                                                          nullptr, nullptr, yh_, yl_,
                                                          BTOK, 3072, 768, 1);
        split_kernel<<<(768 * 3072 + 255) / 256, 256>>>(fc2_w + (long)l * 768 * 3072, wh_, wl_,
                                                        768L * 3072);
        gemm_mma_kernel<<<dim3(6, 17), 256, GEMM_SMEM>>>(yh_, yl_, wh_, wl_, fc2_b + l * DIM, t_,
                                                         t_, nullptr, nullptr, BTOK, 768, 3072, 0);
        if (feat_k < 4 && l == OUT_IDX[feat_k]) {
            cudaMemcpyAsync(feats_ + (long)feat_k * FEAT, t_, (long)FEAT * sizeof(float),
                            cudaMemcpyDeviceToDevice);
            feat_k++;
        }
    }

    const long O1 = 2L * 768 * 128 * 128;
    const long O2 = 2L * 768 * 64 * 64;
    const long O3 = 2L * 768 * 32 * 32;

    // fpn1 stage A: deconv d1 on feats[0]
    transw_kernel<<<(3072 * 768 + 255) / 256, 256>>>(d1_w, wt_);
    split_kernel<<<(3072 * 768 + 255) / 256, 256>>>(wt_, wh_, wl_, 3072L * 768);
    for (int b = 0; b < 2; b++) {
        split_kernel<<<(1024 * 768 + 255) / 256, 256>>>(
            feats_ + 0L * FEAT + (long)b * NTOK * DIM + DIM, xh_, xl_, 1024L * 768);
        gemm_mma_kernel<<<dim3(24, 8), 256, GEMM_SMEM>>>(xh_, xl_, wh_, wl_, nullptr, nullptr,
                                                         gm_ + (long)b * 1024 * 3072,
                                                         nullptr, nullptr, 1024, 3072, 768, 0);
    }
    scatter_mid_kernel<<<(2 * 1024 * 3072 + 255) / 256, 256>>>(gm_, d1_b, bn_w, bn_b,
                                                               bn_mean, bn_var, yh_, yl_);
    // fpn1 stage B: deconv d2 -> o1
    transw_kernel<<<(3072 * 768 + 255) / 256, 256>>>(d2_w, wt_);
    split_kernel<<<(3072 * 768 + 255) / 256, 256>>>(wt_, wh_, wl_, 3072L * 768);
    gemm_mma_kernel<<<dim3(24, 64), 256, GEMM_SMEM>>>(yh_, yl_, wh_, wl_, nullptr, nullptr,
                                                      gm_, nullptr, nullptr, 8192, 3072, 768, 0);
    scatter_o1_kernel<<<(8192 * 3072 + 255) / 256, 256>>>(gm_, d2_b, out);

    // fpn2: deconv f2 on feats[1] -> o2
    transw_kernel<<<(3072 * 768 + 255) / 256, 256>>>(f2_w, wt_);
    split_kernel<<<(3072 * 768 + 255) / 256, 256>>>(wt_, wh_, wl_, 3072L * 768);
    for (int b = 0; b < 2; b++) {
        split_kernel<<<(1024 * 768 + 255) / 256, 256>>>(
            feats_ + 1L * FEAT + (long)b * NTOK * DIM + DIM, xh_, xl_, 1024L * 768);
        gemm_mma_kernel<<<dim3(24, 8), 256, GEMM_SMEM>>>(xh_, xl_, wh_, wl_, nullptr, nullptr,
                                                         gm_ + (long)b * 1024 * 3072,
                                                         nullptr, nullptr, 1024, 3072, 768, 0);
    }
    scatter_o2_kernel<<<(2 * 1024 * 3072 + 255) / 256, 256>>>(gm_, f2_b, out + O1);

    o3_kernel<<<(2 * 768 * 1024 + 255) / 256, 256>>>(feats_ + 2L * FEAT, out + O1 + O2);
    o4_kernel<<<(2 * 768 * 256 + 255) / 256, 256>>>(feats_ + 3L * FEAT, out + O1 + O2 + O3);
}